// round 2
// baseline (speedup 1.0000x reference)
#include <cuda_runtime.h>
#include <math.h>
#include <stdint.h>

#define B_  2
#define L_  1024
#define DM  1024
#define DI  2048
#define NH  32
#define HD  64
#define DS  128
#define NA  32
#define DP  4480   // 2*DI + 2*DS + 3*NH + NA
#define BT  (B_*L_)

// ---------------- device scratch (no mallocs allowed) ----------------
__device__ float g_proj[(size_t)BT * DP];   // 36.7 MB
__device__ float g_Bn  [BT * DS];
__device__ float g_Cn  [BT * DS];
__device__ float g_dt  [BT * NH];
__device__ float g_gd  [BT * NH];
__device__ float g_lam [BT * NH];
__device__ float g_cos [BT * NH * NA];
__device__ float g_sin [BT * NH * NA];
__device__ float g_y   [(size_t)BT * DI];   // 16.8 MB (y, then gated activation in-place)

__device__ __forceinline__ float softplusf(float x) {
    return (x > 20.f) ? x : log1pf(expf(x));
}

// ---------------- fp32 NT GEMM: C[M,N] = A[M,K] * B[N,K]^T ----------------
// BM=BN=64, BK=16, 256 threads, 4x4 per thread.
__global__ __launch_bounds__(256) void gemm_nt(
    const float* __restrict__ A, const float* __restrict__ B,
    float* __restrict__ C, int M, int N, int K)
{
    __shared__ float As[16][68];
    __shared__ float Bs[16][68];
    const int tid = threadIdx.x;
    const int bm = blockIdx.y * 64;
    const int bn = blockIdx.x * 64;
    const int lr = tid >> 2;          // 0..63 tile row for loads
    const int lk = (tid & 3) << 2;    // k offset 0,4,8,12
    const int tm = (tid >> 4) << 2;   // 0..60
    const int tn = (tid & 15) << 2;   // 0..60

    float acc[4][4];
#pragma unroll
    for (int i = 0; i < 4; i++)
#pragma unroll
        for (int j = 0; j < 4; j++) acc[i][j] = 0.f;

    const float* Aptr = A + (size_t)(bm + lr) * K + lk;
    const float* Bptr = B + (size_t)(bn + lr) * K + lk;

    for (int k0 = 0; k0 < K; k0 += 16) {
        float4 av = *(const float4*)(Aptr + k0);
        float4 bv = *(const float4*)(Bptr + k0);
        __syncthreads();
        As[lk + 0][lr] = av.x; As[lk + 1][lr] = av.y;
        As[lk + 2][lr] = av.z; As[lk + 3][lr] = av.w;
        Bs[lk + 0][lr] = bv.x; Bs[lk + 1][lr] = bv.y;
        Bs[lk + 2][lr] = bv.z; Bs[lk + 3][lr] = bv.w;
        __syncthreads();
#pragma unroll
        for (int k = 0; k < 16; k++) {
            float4 a4 = *(const float4*)&As[k][tm];
            float4 b4 = *(const float4*)&Bs[k][tn];
            acc[0][0] = fmaf(a4.x, b4.x, acc[0][0]);
            acc[0][1] = fmaf(a4.x, b4.y, acc[0][1]);
            acc[0][2] = fmaf(a4.x, b4.z, acc[0][2]);
            acc[0][3] = fmaf(a4.x, b4.w, acc[0][3]);
            acc[1][0] = fmaf(a4.y, b4.x, acc[1][0]);
            acc[1][1] = fmaf(a4.y, b4.y, acc[1][1]);
            acc[1][2] = fmaf(a4.y, b4.z, acc[1][2]);
            acc[1][3] = fmaf(a4.y, b4.w, acc[1][3]);
            acc[2][0] = fmaf(a4.z, b4.x, acc[2][0]);
            acc[2][1] = fmaf(a4.z, b4.y, acc[2][1]);
            acc[2][2] = fmaf(a4.z, b4.z, acc[2][2]);
            acc[2][3] = fmaf(a4.z, b4.w, acc[2][3]);
            acc[3][0] = fmaf(a4.w, b4.x, acc[3][0]);
            acc[3][1] = fmaf(a4.w, b4.y, acc[3][1]);
            acc[3][2] = fmaf(a4.w, b4.z, acc[3][2]);
            acc[3][3] = fmaf(a4.w, b4.w, acc[3][3]);
        }
    }
#pragma unroll
    for (int i = 0; i < 4; i++) {
        float4 v = make_float4(acc[i][0], acc[i][1], acc[i][2], acc[i][3]);
        *(float4*)(C + (size_t)(bm + tm + i) * N + bn + tn) = v;
    }
}

// ---------------- prep: rmsnorm(B), rmsnorm(C), per-head scalars ----------------
__global__ __launch_bounds__(128) void prep_kernel(
    const float* __restrict__ dt_bias,
    const float* __restrict__ Bnw, const float* __restrict__ Cnw)
{
    const int bt = blockIdx.x;
    const int n  = threadIdx.x;     // 0..127
    const size_t base = (size_t)bt * DP;

    float Bv = g_proj[base + 2 * DI + n];
    float Cv = g_proj[base + 2 * DI + DS + n];
    float sb = Bv * Bv, sc = Cv * Cv;
#pragma unroll
    for (int o = 16; o > 0; o >>= 1) {
        sb += __shfl_xor_sync(0xffffffffu, sb, o);
        sc += __shfl_xor_sync(0xffffffffu, sc, o);
    }
    __shared__ float red[2][4];
    const int w = n >> 5, ln = n & 31;
    if (ln == 0) { red[0][w] = sb; red[1][w] = sc; }
    __syncthreads();
    float tb = red[0][0] + red[0][1] + red[0][2] + red[0][3];
    float tc = red[1][0] + red[1][1] + red[1][2] + red[1][3];

    g_Bn[bt * DS + n] = Bv * rsqrtf(tb * (1.f / DS) + 1e-5f) * Bnw[n];
    g_Cn[bt * DS + n] = Cv * rsqrtf(tc * (1.f / DS) + 1e-5f) * Cnw[n];

    if (n < NH) {
        float dd = g_proj[base + 2 * DI + 2 * DS + n];
        float dA = g_proj[base + 2 * DI + 2 * DS + NH + n];
        float tr = g_proj[base + 2 * DI + 2 * DS + 2 * NH + n];
        float dt = softplusf(dd + dt_bias[n]);
        float a  = -softplusf(dA);
        a = fminf(a, -1e-4f);
        g_dt [bt * NH + n] = dt;
        g_gd [bt * NH + n] = expf(a * dt);
        g_lam[bt * NH + n] = 1.f / (1.f + expf(-tr));
    }
}

// ---------------- theta cumsum + sincos: one warp per (b,h) ----------------
__global__ __launch_bounds__(32) void theta_kernel()
{
    const int h = blockIdx.x;
    const int b = blockIdx.y;
    const int j = threadIdx.x;   // 0..31 angle index

    float acc = 0.f;
    const size_t abase = (size_t)(b * L_) * DP + (DP - NA) + j;

    float ang = g_proj[abase];
    float dtv = g_dt[(b * L_) * NH + h];
    for (int t = 0; t < L_; t++) {
        float ang_n = 0.f, dt_n = 0.f;
        if (t + 1 < L_) {
            ang_n = g_proj[abase + (size_t)(t + 1) * DP];
            dt_n  = g_dt[(b * L_ + t + 1) * NH + h];
        }
        acc = fmaf(ang, dtv, acc);
        float s, c;
        sincosf(acc, &s, &c);
        const int o = ((b * L_ + t) * NH + h) * NA + j;
        g_cos[o] = c;
        g_sin[o] = s;
        ang = ang_n; dtv = dt_n;
    }
}

// ---------------- sequential SSM scan ----------------
// grid (2 p-halves, NH, B), 128 threads. Each thread owns 32 state elems:
// p = pstart + (tid>>2), n in [(tid&3)*32, +32).
#define SCAN_LOAD(T)                                                        \
    {                                                                       \
        const int bt_ = b * L_ + (T);                                       \
        if (tid < 32) {                                                     \
            r0 = g_Bn[bt_ * DS + tid];                                      \
            r1 = g_Bn[bt_ * DS + tid + 32];                                 \
            rc = g_cos[(bt_ * NH + h) * NA + tid];                          \
            rs = g_sin[(bt_ * NH + h) * NA + tid];                          \
            rx = g_proj[(size_t)bt_ * DP + DI + h * HD + pstart + tid];     \
        } else if (tid < 64) {                                              \
            const int j_ = tid - 32;                                        \
            r0 = g_Cn[bt_ * DS + j_];                                       \
            r1 = g_Cn[bt_ * DS + j_ + 32];                                  \
            rc = g_cos[(bt_ * NH + h) * NA + j_];                           \
            rs = g_sin[(bt_ * NH + h) * NA + j_];                           \
        } else {                                                            \
            r0 = g_Bn[bt_ * DS + tid];                                      \
            r1 = g_Cn[bt_ * DS + tid];                                      \
        }                                                                   \
        rdt  = g_dt [bt_ * NH + h];                                         \
        rg   = g_gd [bt_ * NH + h];                                         \
        rlam = g_lam[bt_ * NH + h];                                         \
    }

__global__ __launch_bounds__(128) void scan_kernel(
    const float* __restrict__ Bbias, const float* __restrict__ Cbias)
{
    const int phalf = blockIdx.x;
    const int h = blockIdx.y;
    const int b = blockIdx.z;
    const int tid = threadIdx.x;
    const int lp = tid >> 2;
    const int nq = tid & 3;
    const int n0 = nq * 32;
    const int pstart = phalf * 32;

    __shared__ float sB[2][DS];
    __shared__ float sC[2][DS];
    __shared__ float sx[2][32];

    // hoisted per-role biases
    float bias1, bias2;
    if (tid < 32)      { bias1 = Bbias[h * DS + tid];      bias2 = Bbias[h * DS + tid + 32]; }
    else if (tid < 64) { bias1 = Cbias[h * DS + tid - 32]; bias2 = Cbias[h * DS + tid]; }
    else               { bias1 = Bbias[h * DS + tid];      bias2 = Cbias[h * DS + tid]; }

    float r0 = 0, r1 = 0, rc = 0, rs = 0, rx = 0, rdt = 0, rg = 0, rlam = 0;
    SCAN_LOAD(0);

    float hreg[32], Bp[32];
#pragma unroll
    for (int i = 0; i < 32; i++) { hreg[i] = 0.f; Bp[i] = 0.f; }
    float xprev = 0.f;

    for (int t = 0; t < L_; t++) {
        const int buf = t & 1;
        // ---- produce Bh/Ch/x into smem (RoPE on the fly) ----
        if (tid < 32) {
            float v1 = r0 + bias1, v2 = r1 + bias2;
            sB[buf][tid]      = v1 * rc - v2 * rs;
            sB[buf][tid + 32] = v1 * rs + v2 * rc;
            sx[buf][tid] = rx;
        } else if (tid < 64) {
            const int j = tid - 32;
            float v1 = r0 + bias1, v2 = r1 + bias2;
            sC[buf][j]      = v1 * rc - v2 * rs;
            sC[buf][j + 32] = v1 * rs + v2 * rc;
        } else {
            sB[buf][tid] = r0 + bias1;
            sC[buf][tid] = r1 + bias2;
        }
        const float dt = rdt, g = rg, lam = rlam;
        __syncthreads();
        // ---- prefetch t+1 (overlaps compute below) ----
        if (t + 1 < L_) SCAN_LOAD(t + 1);

        // ---- state update ----
        const float xc = sx[buf][lp];
        const float c1 = dt * lam * xc;
        const float c2 = dt * (1.f - lam) * g * xprev;
        float y = 0.f;
        const float4* pB4 = (const float4*)&sB[buf][n0];
        const float4* pC4 = (const float4*)&sC[buf][n0];
#pragma unroll
        for (int q = 0; q < 8; q++) {
            float4 bv = pB4[q];
            float4 cv = pC4[q];
            const int i = q * 4;
            hreg[i + 0] = fmaf(g, hreg[i + 0], fmaf(c1, bv.x, c2 * Bp[i + 0]));
            y = fmaf(hreg[i + 0], cv.x, y);
            Bp[i + 0] = bv.x;
            hreg[i + 1] = fmaf(g, hreg[i + 1], fmaf(c1, bv.y, c2 * Bp[i + 1]));
            y = fmaf(hreg[i + 1], cv.y, y);
            Bp[i + 1] = bv.y;
            hreg[i + 2] = fmaf(g, hreg[i + 2], fmaf(c1, bv.z, c2 * Bp[i + 2]));
            y = fmaf(hreg[i + 2], cv.z, y);
            Bp[i + 2] = bv.z;
            hreg[i + 3] = fmaf(g, hreg[i + 3], fmaf(c1, bv.w, c2 * Bp[i + 3]));
            y = fmaf(hreg[i + 3], cv.w, y);
            Bp[i + 3] = bv.w;
        }
        xprev = xc;
        y += __shfl_xor_sync(0xffffffffu, y, 1);
        y += __shfl_xor_sync(0xffffffffu, y, 2);
        if (nq == 0)
            g_y[(size_t)(b * L_ + t) * DI + h * HD + pstart + lp] = y;
    }
}

// ---------------- epilogue: yact = (y + D[h]*x) * silu(z), in place ----------------
__global__ __launch_bounds__(256) void epi_kernel(const float* __restrict__ Dp)
{
    const int idx = blockIdx.x * 256 + threadIdx.x;
    const int bt = idx >> 11;     // / 2048
    const int c  = idx & 2047;
    const int h  = c >> 6;
    float y = g_y[idx];
    float x = g_proj[(size_t)bt * DP + DI + c];
    float z = g_proj[(size_t)bt * DP + c];
    float sil = z / (1.f + expf(-z));
    g_y[idx] = (y + Dp[h] * x) * sil;
}

// ---------------- launch ----------------
extern "C" void kernel_launch(void* const* d_in, const int* in_sizes, int n_in,
                              void* d_out, int out_size)
{
    (void)in_sizes; (void)n_in; (void)out_size;
    const float* u        = (const float*)d_in[0];
    const float* W_in     = (const float*)d_in[1];
    const float* W_out    = (const float*)d_in[2];
    const float* dt_bias  = (const float*)d_in[3];
    const float* B_bias   = (const float*)d_in[4];
    const float* C_bias   = (const float*)d_in[5];
    const float* B_norm_w = (const float*)d_in[6];
    const float* C_norm_w = (const float*)d_in[7];
    const float* D_param  = (const float*)d_in[8];
    float* out = (float*)d_out;

    void *p_proj = nullptr, *p_y = nullptr;
    cudaGetSymbolAddress(&p_proj, g_proj);
    cudaGetSymbolAddress(&p_y, g_y);

    // 1) proj = u @ W_in^T   (M=2048, N=4480, K=1024)
    gemm_nt<<<dim3(DP / 64, BT / 64), 256>>>(u, W_in, (float*)p_proj, BT, DP, DM);

    // 2) rmsnorm + head scalars
    prep_kernel<<<BT, 128>>>(dt_bias, B_norm_w, C_norm_w);

    // 3) theta cumsum + sincos
    theta_kernel<<<dim3(NH, B_), 32>>>();

    // 4) sequential scan
    scan_kernel<<<dim3(2, NH, B_), 128>>>(B_bias, C_bias);

    // 5) gated epilogue
    epi_kernel<<<(BT * DI) / 256, 256>>>(D_param);

    // 6) out = yact @ W_out^T  (M=2048, N=1024, K=2048)
    gemm_nt<<<dim3(DM / 64, BT / 64), 256>>>((const float*)p_y, W_out, out, BT, DM, DI);
}

// round 4
// speedup vs baseline: 1.3172x; 1.3172x over previous
#include <cuda_runtime.h>
#include <cuda_bf16.h>
#include <math.h>
#include <stdint.h>

#define B_  2
#define L_  1024
#define DM  1024
#define DI  2048
#define NH  32
#define HD  64
#define DS  128
#define NA  32
#define DP  4480   // 2*DI + 2*DS + 3*NH + NA
#define BT  (B_*L_)

#define K1  DM          // gemm1 logical K
#define K1X (3*DM)      // gemm1 folded K' = 3072
#define K2  DI
#define K2X (3*DI)      // gemm2 folded K' = 6144

// ---------------- device scratch (no mallocs allowed) ----------------
__device__ float g_proj[(size_t)BT * DP];   // 36.7 MB
__device__ float g_Bn  [BT * DS];
__device__ float g_Cn  [BT * DS];
__device__ float g_dt  [BT * NH];
__device__ float g_gd  [BT * NH];
__device__ float g_lam [BT * NH];
__device__ float g_cos [BT * NH * NA];
__device__ float g_sin [BT * NH * NA];
__device__ float g_y   [(size_t)BT * DI];   // scan output (pre-gate)

// folded split-bf16 operands:  A-pattern rows = [hi | lo | hi], B-pattern rows = [hi | hi | lo]
__device__ __nv_bfloat16 g_u2 [(size_t)BT * K1X];   // 12.6 MB
__device__ __nv_bfloat16 g_Wi2[(size_t)DP * K1X];   // 27.5 MB
__device__ __nv_bfloat16 g_y2 [(size_t)BT * K2X];   // 25.2 MB
__device__ __nv_bfloat16 g_Wo2[(size_t)DM * K2X];   // 12.6 MB

__device__ __forceinline__ float softplusf(float x) {
    return (x > 20.f) ? x : log1pf(expf(x));
}
__device__ __forceinline__ uint32_t smem_u32(const void* p) {
    uint32_t a;
    asm("{ .reg .u64 t; cvta.to.shared.u64 t, %1; cvt.u32.u64 %0, t; }" : "=r"(a) : "l"(p));
    return a;
}

#define CP_ASYNC16(dst, src) \
    asm volatile("cp.async.cg.shared.global [%0], [%1], 16;" :: "r"(dst), "l"(src))
#define CP_COMMIT() asm volatile("cp.async.commit_group;")
#define CP_WAIT1()  asm volatile("cp.async.wait_group 1;")
#define CP_WAIT0()  asm volatile("cp.async.wait_group 0;")

__device__ __forceinline__ void ldsm_x4(uint32_t* r, uint32_t addr) {
    asm volatile("ldmatrix.sync.aligned.m8n8.x4.shared.b16 {%0,%1,%2,%3}, [%4];"
        : "=r"(r[0]), "=r"(r[1]), "=r"(r[2]), "=r"(r[3]) : "r"(addr));
}
__device__ __forceinline__ void mma16816(float* d, const uint32_t* a, const uint32_t* b) {
    asm volatile(
        "mma.sync.aligned.m16n8k16.row.col.f32.bf16.bf16.f32 "
        "{%0,%1,%2,%3},{%4,%5,%6,%7},{%8,%9},{%0,%1,%2,%3};"
        : "+f"(d[0]), "+f"(d[1]), "+f"(d[2]), "+f"(d[3])
        : "r"(a[0]), "r"(a[1]), "r"(a[2]), "r"(a[3]), "r"(b[0]), "r"(b[1]));
}

// ---------------- split kernels: f32 -> folded bf16 rows ----------------
// A-pattern: dst row (len 3K) = [hi | lo | hi]
__global__ __launch_bounds__(256) void split_A(
    const float* __restrict__ src, __nv_bfloat16* __restrict__ dst, int Kq, int n4)
{
    int i = blockIdx.x * 256 + threadIdx.x;
    if (i >= n4) return;
    int row = i / Kq, k4 = (i - row * Kq) * 4;
    float4 v = *(const float4*)(src + (size_t)row * (Kq * 4) + k4);
    __nv_bfloat162 h01 = __floats2bfloat162_rn(v.x, v.y);
    __nv_bfloat162 h23 = __floats2bfloat162_rn(v.z, v.w);
    __nv_bfloat162 l01 = __floats2bfloat162_rn(v.x - __low2float(h01), v.y - __high2float(h01));
    __nv_bfloat162 l23 = __floats2bfloat162_rn(v.z - __low2float(h23), v.w - __high2float(h23));
    const int K = Kq * 4;
    __nv_bfloat162* d0 = (__nv_bfloat162*)(dst + (size_t)row * 3 * K + k4);
    __nv_bfloat162* d1 = (__nv_bfloat162*)(dst + (size_t)row * 3 * K + K + k4);
    __nv_bfloat162* d2 = (__nv_bfloat162*)(dst + (size_t)row * 3 * K + 2 * K + k4);
    d0[0] = h01; d0[1] = h23;
    d1[0] = l01; d1[1] = l23;
    d2[0] = h01; d2[1] = h23;
}
// B-pattern: dst row = [hi | hi | lo]
__global__ __launch_bounds__(256) void split_B(
    const float* __restrict__ src, __nv_bfloat16* __restrict__ dst, int Kq, int n4)
{
    int i = blockIdx.x * 256 + threadIdx.x;
    if (i >= n4) return;
    int row = i / Kq, k4 = (i - row * Kq) * 4;
    float4 v = *(const float4*)(src + (size_t)row * (Kq * 4) + k4);
    __nv_bfloat162 h01 = __floats2bfloat162_rn(v.x, v.y);
    __nv_bfloat162 h23 = __floats2bfloat162_rn(v.z, v.w);
    __nv_bfloat162 l01 = __floats2bfloat162_rn(v.x - __low2float(h01), v.y - __high2float(h01));
    __nv_bfloat162 l23 = __floats2bfloat162_rn(v.z - __low2float(h23), v.w - __high2float(h23));
    const int K = Kq * 4;
    __nv_bfloat162* d0 = (__nv_bfloat162*)(dst + (size_t)row * 3 * K + k4);
    __nv_bfloat162* d1 = (__nv_bfloat162*)(dst + (size_t)row * 3 * K + K + k4);
    __nv_bfloat162* d2 = (__nv_bfloat162*)(dst + (size_t)row * 3 * K + 2 * K + k4);
    d0[0] = h01; d0[1] = h23;
    d1[0] = h01; d1[1] = h23;
    d2[0] = l01; d2[1] = l23;
}

// ---------------- bf16 mma.sync GEMM: C[M,N] = A[M,K] * B[N,K]^T ----------------
// CTA 128x128, BK=64, 256 threads (8 warps as 4Mx2N), cp.async double buffer,
// SW128 swizzle (conflict-free ldmatrix).
#define GS_STAGE 32768                    // A 16KB + B 16KB per stage
#define GS_TOTAL (2 * GS_STAGE + 1024)

__global__ __launch_bounds__(256) void gemm_bf16(
    const __nv_bfloat16* __restrict__ A, const __nv_bfloat16* __restrict__ Bm,
    float* __restrict__ C, int M, int N, int K)
{
    extern __shared__ char dynsmem[];
    const int tid = threadIdx.x;
    const int wid = tid >> 5, lane = tid & 31;
    const int bm = blockIdx.y * 128, bn = blockIdx.x * 128;
    const int m_warp = (wid >> 1) * 32, n_warp = (wid & 1) * 64;

    uint32_t raw = smem_u32(dynsmem);
    const uint32_t sbase = (raw + 1023u) & ~1023u;

    // producer: 4 chunks A + 4 chunks B per thread, 16B each
    uint32_t psw[4];
    const __nv_bfloat16 *Ap[4], *Bp[4];
#pragma unroll
    for (int i = 0; i < 4; i++) {
        const int chunk = tid + i * 256;       // 0..1023
        const int row = chunk >> 3, c = chunk & 7;
        psw[i] = row * 128 + ((c ^ (row & 7)) << 4);
        Ap[i] = A  + (size_t)(bm + row) * K + c * 8;
        Bp[i] = Bm + (size_t)(bn + row) * K + c * 8;
    }

    // consumer address precalc
    const int khA = lane >> 4;
    const int rA0 = m_warp + (lane & 15), rA1 = rA0 + 16;
    const uint32_t offA0 = rA0 * 128, offA1 = rA1 * 128;
    const int x7A0 = rA0 & 7, x7A1 = rA1 & 7;
    const int khB = (lane >> 3) & 1;
    const int rb_off = (lane & 7) + ((lane >> 4) << 3);
    uint32_t offB[4]; int x7B[4];
#pragma unroll
    for (int np = 0; np < 4; np++) {
        const int r = n_warp + np * 16 + rb_off;
        offB[np] = r * 128; x7B[np] = r & 7;
    }

    float acc[2][8][4];
#pragma unroll
    for (int mt = 0; mt < 2; mt++)
#pragma unroll
        for (int nt = 0; nt < 8; nt++)
#pragma unroll
            for (int e = 0; e < 4; e++) acc[mt][nt][e] = 0.f;

    const int nk = K >> 6;

    // prefetch stage 0
    {
        const uint32_t s = sbase;
#pragma unroll
        for (int i = 0; i < 4; i++) {
            CP_ASYNC16(s + psw[i], Ap[i]);
            CP_ASYNC16(s + 16384 + psw[i], Bp[i]);
        }
        CP_COMMIT();
    }

    for (int kc = 0; kc < nk; kc++) {
        const int buf = kc & 1;
        if (kc + 1 < nk) {
            const uint32_t s = sbase + (buf ^ 1) * GS_STAGE;
            const int ko = (kc + 1) << 6;
#pragma unroll
            for (int i = 0; i < 4; i++) {
                CP_ASYNC16(s + psw[i], Ap[i] + ko);
                CP_ASYNC16(s + 16384 + psw[i], Bp[i] + ko);
            }
            CP_COMMIT();
            CP_WAIT1();
        } else {
            CP_WAIT0();
        }
        __syncthreads();

        const uint32_t sA = sbase + buf * GS_STAGE;
        const uint32_t sB = sA + 16384;
#pragma unroll
        for (int ks = 0; ks < 4; ks++) {
            uint32_t a0[4], a1[4];
            const int cA = 2 * ks + khA;
            ldsm_x4(a0, sA + offA0 + ((cA ^ x7A0) << 4));
            ldsm_x4(a1, sA + offA1 + ((cA ^ x7A1) << 4));
            uint32_t b[8][2];
            const int cB = 2 * ks + khB;
#pragma unroll
            for (int np = 0; np < 4; np++) {
                uint32_t r[4];
                ldsm_x4(r, sB + offB[np] + ((cB ^ x7B[np]) << 4));
                b[2 * np][0] = r[0]; b[2 * np][1] = r[1];
                b[2 * np + 1][0] = r[2]; b[2 * np + 1][1] = r[3];
            }
#pragma unroll
            for (int nt = 0; nt < 8; nt++) {
                mma16816(acc[0][nt], a0, b[nt]);
                mma16816(acc[1][nt], a1, b[nt]);
            }
        }
        __syncthreads();
    }

    // epilogue
    const int tr = lane >> 2, tc = (lane & 3) * 2;
#pragma unroll
    for (int mt = 0; mt < 2; mt++) {
        const int row0 = bm + m_warp + mt * 16 + tr;
#pragma unroll
        for (int nt = 0; nt < 8; nt++) {
            const int col = bn + n_warp + nt * 8 + tc;
            *(float2*)(C + (size_t)row0 * N + col)       = make_float2(acc[mt][nt][0], acc[mt][nt][1]);
            *(float2*)(C + (size_t)(row0 + 8) * N + col) = make_float2(acc[mt][nt][2], acc[mt][nt][3]);
        }
    }
}

// ---------------- prep: rmsnorm(B), rmsnorm(C), per-head scalars ----------------
__global__ __launch_bounds__(128) void prep_kernel(
    const float* __restrict__ dt_bias,
    const float* __restrict__ Bnw, const float* __restrict__ Cnw)
{
    const int bt = blockIdx.x;
    const int n  = threadIdx.x;     // 0..127
    const size_t base = (size_t)bt * DP;

    float Bv = g_proj[base + 2 * DI + n];
    float Cv = g_proj[base + 2 * DI + DS + n];
    float sb = Bv * Bv, sc = Cv * Cv;
#pragma unroll
    for (int o = 16; o > 0; o >>= 1) {
        sb += __shfl_xor_sync(0xffffffffu, sb, o);
        sc += __shfl_xor_sync(0xffffffffu, sc, o);
    }
    __shared__ float red[2][4];
    const int w = n >> 5, ln = n & 31;
    if (ln == 0) { red[0][w] = sb; red[1][w] = sc; }
    __syncthreads();
    float tb = red[0][0] + red[0][1] + red[0][2] + red[0][3];
    float tc = red[1][0] + red[1][1] + red[1][2] + red[1][3];

    g_Bn[bt * DS + n] = Bv * rsqrtf(tb * (1.f / DS) + 1e-5f) * Bnw[n];
    g_Cn[bt * DS + n] = Cv * rsqrtf(tc * (1.f / DS) + 1e-5f) * Cnw[n];

    if (n < NH) {
        float dd = g_proj[base + 2 * DI + 2 * DS + n];
        float dA = g_proj[base + 2 * DI + 2 * DS + NH + n];
        float tr = g_proj[base + 2 * DI + 2 * DS + 2 * NH + n];
        float dt = softplusf(dd + dt_bias[n]);
        float a  = -softplusf(dA);
        a = fminf(a, -1e-4f);
        g_dt [bt * NH + n] = dt;
        g_gd [bt * NH + n] = expf(a * dt);
        g_lam[bt * NH + n] = 1.f / (1.f + expf(-tr));
    }
}

// ---------------- theta cumsum + sincos: one warp per (b,h) ----------------
__global__ __launch_bounds__(32) void theta_kernel()
{
    const int h = blockIdx.x;
    const int b = blockIdx.y;
    const int j = threadIdx.x;   // 0..31 angle index

    float acc = 0.f;
    const size_t abase = (size_t)(b * L_) * DP + (DP - NA) + j;

    float ang = g_proj[abase];
    float dtv = g_dt[(b * L_) * NH + h];
    for (int t = 0; t < L_; t++) {
        float ang_n = 0.f, dt_n = 0.f;
        if (t + 1 < L_) {
            ang_n = g_proj[abase + (size_t)(t + 1) * DP];
            dt_n  = g_dt[(b * L_ + t + 1) * NH + h];
        }
        acc = fmaf(ang, dtv, acc);
        float s, c;
        sincosf(acc, &s, &c);
        const int o = ((b * L_ + t) * NH + h) * NA + j;
        g_cos[o] = c;
        g_sin[o] = s;
        ang = ang_n; dtv = dt_n;
    }
}

// ---------------- sequential SSM scan ----------------
#define SCAN_LOAD(T)                                                        \
    {                                                                       \
        const int bt_ = b * L_ + (T);                                       \
        if (tid < 32) {                                                     \
            r0 = g_Bn[bt_ * DS + tid];                                      \
            r1 = g_Bn[bt_ * DS + tid + 32];                                 \
            rc = g_cos[(bt_ * NH + h) * NA + tid];                          \
            rs = g_sin[(bt_ * NH + h) * NA + tid];                          \
            rx = g_proj[(size_t)bt_ * DP + DI + h * HD + pstart + tid];     \
        } else if (tid < 64) {                                              \
            const int j_ = tid - 32;                                        \
            r0 = g_Cn[bt_ * DS + j_];                                       \
            r1 = g_Cn[bt_ * DS + j_ + 32];                                  \
            rc = g_cos[(bt_ * NH + h) * NA + j_];                           \
            rs = g_sin[(bt_ * NH + h) * NA + j_];                           \
        } else {                                                            \
            r0 = g_Bn[bt_ * DS + tid];                                      \
            r1 = g_Cn[bt_ * DS + tid];                                      \
        }                                                                   \
        rdt  = g_dt [bt_ * NH + h];                                         \
        rg   = g_gd [bt_ * NH + h];                                         \
        rlam = g_lam[bt_ * NH + h];                                         \
    }

__global__ __launch_bounds__(128) void scan_kernel(
    const float* __restrict__ Bbias, const float* __restrict__ Cbias)
{
    const int phalf = blockIdx.x;
    const int h = blockIdx.y;
    const int b = blockIdx.z;
    const int tid = threadIdx.x;
    const int lp = tid >> 2;
    const int nq = tid & 3;
    const int n0 = nq * 32;
    const int pstart = phalf * 32;

    __shared__ float sB[2][DS];
    __shared__ float sC[2][DS];
    __shared__ float sx[2][32];

    float bias1, bias2;
    if (tid < 32)      { bias1 = Bbias[h * DS + tid];      bias2 = Bbias[h * DS + tid + 32]; }
    else if (tid < 64) { bias1 = Cbias[h * DS + tid - 32]; bias2 = Cbias[h * DS + tid]; }
    else               { bias1 = Bbias[h * DS + tid];      bias2 = Cbias[h * DS + tid]; }

    float r0 = 0, r1 = 0, rc = 0, rs = 0, rx = 0, rdt = 0, rg = 0, rlam = 0;
    SCAN_LOAD(0);

    float hreg[32], Bp[32];
#pragma unroll
    for (int i = 0; i < 32; i++) { hreg[i] = 0.f; Bp[i] = 0.f; }
    float xprev = 0.f;

    for (int t = 0; t < L_; t++) {
        const int buf = t & 1;
        if (tid < 32) {
            float v1 = r0 + bias1, v2 = r1 + bias2;
            sB[buf][tid]      = v1 * rc - v2 * rs;
            sB[buf][tid + 32] = v1 * rs + v2 * rc;
            sx[buf][tid] = rx;
        } else if (tid < 64) {
            const int j = tid - 32;
            float v1 = r0 + bias1, v2 = r1 + bias2;
            sC[buf][j]      = v1 * rc - v2 * rs;
            sC[buf][j + 32] = v1 * rs + v2 * rc;
        } else {
            sB[buf][tid] = r0 + bias1;
            sC[buf][tid] = r1 + bias2;
        }
        const float dt = rdt, g = rg, lam = rlam;
        __syncthreads();
        if (t + 1 < L_) SCAN_LOAD(t + 1);

        const float xc = sx[buf][lp];
        const float c1 = dt * lam * xc;
        const float c2 = dt * (1.f - lam) * g * xprev;
        float y = 0.f;
        const float4* pB4 = (const float4*)&sB[buf][n0];
        const float4* pC4 = (const float4*)&sC[buf][n0];
#pragma unroll
        for (int q = 0; q < 8; q++) {
            float4 bv = pB4[q];
            float4 cv = pC4[q];
            const int i = q * 4;
            hreg[i + 0] = fmaf(g, hreg[i + 0], fmaf(c1, bv.x, c2 * Bp[i + 0]));
            y = fmaf(hreg[i + 0], cv.x, y);
            Bp[i + 0] = bv.x;
            hreg[i + 1] = fmaf(g, hreg[i + 1], fmaf(c1, bv.y, c2 * Bp[i + 1]));
            y = fmaf(hreg[i + 1], cv.y, y);
            Bp[i + 1] = bv.y;
            hreg[i + 2] = fmaf(g, hreg[i + 2], fmaf(c1, bv.z, c2 * Bp[i + 2]));
            y = fmaf(hreg[i + 2], cv.z, y);
            Bp[i + 2] = bv.z;
            hreg[i + 3] = fmaf(g, hreg[i + 3], fmaf(c1, bv.w, c2 * Bp[i + 3]));
            y = fmaf(hreg[i + 3], cv.w, y);
            Bp[i + 3] = bv.w;
        }
        xprev = xc;
        y += __shfl_xor_sync(0xffffffffu, y, 1);
        y += __shfl_xor_sync(0xffffffffu, y, 2);
        if (nq == 0)
            g_y[(size_t)(b * L_ + t) * DI + h * HD + pstart + lp] = y;
    }
}

// ---------------- epilogue: yact = (y + D[h]*x) * silu(z) -> folded bf16 (A-pattern) ----------------
__global__ __launch_bounds__(256) void epi_kernel(const float* __restrict__ Dp)
{
    const int idx = blockIdx.x * 256 + threadIdx.x;
    const int bt = idx >> 11;     // / 2048
    const int c  = idx & 2047;
    const int h  = c >> 6;
    float y = g_y[idx];
    float x = g_proj[(size_t)bt * DP + DI + c];
    float z = g_proj[(size_t)bt * DP + c];
    float sil = z / (1.f + expf(-z));
    float v = (y + Dp[h] * x) * sil;
    __nv_bfloat16 hh = __float2bfloat16(v);
    __nv_bfloat16 ll = __float2bfloat16(v - __bfloat162float(hh));
    const size_t rb = (size_t)bt * K2X;
    g_y2[rb + c]          = hh;
    g_y2[rb + DI + c]     = ll;
    g_y2[rb + 2 * DI + c] = hh;
}

// ---------------- launch ----------------
extern "C" void kernel_launch(void* const* d_in, const int* in_sizes, int n_in,
                              void* d_out, int out_size)
{
    (void)in_sizes; (void)n_in; (void)out_size;
    const float* u        = (const float*)d_in[0];
    const float* W_in     = (const float*)d_in[1];
    const float* W_out    = (const float*)d_in[2];
    const float* dt_bias  = (const float*)d_in[3];
    const float* B_bias   = (const float*)d_in[4];
    const float* C_bias   = (const float*)d_in[5];
    const float* B_norm_w = (const float*)d_in[6];
    const float* C_norm_w = (const float*)d_in[7];
    const float* D_param  = (const float*)d_in[8];
    float* out = (float*)d_out;

    void *p_proj, *p_u2, *p_wi2, *p_y2, *p_wo2;
    cudaGetSymbolAddress(&p_proj, g_proj);
    cudaGetSymbolAddress(&p_u2,  g_u2);
    cudaGetSymbolAddress(&p_wi2, g_Wi2);
    cudaGetSymbolAddress(&p_y2,  g_y2);
    cudaGetSymbolAddress(&p_wo2, g_Wo2);

    cudaFuncSetAttribute(gemm_bf16, cudaFuncAttributeMaxDynamicSharedMemorySize, GS_TOTAL);

    // 0) folded bf16 splits
    split_A<<<(BT * DM / 4 + 255) / 256, 256>>>(u,     (__nv_bfloat16*)p_u2,  DM / 4, BT * DM / 4);
    split_B<<<(DP * DM / 4 + 255) / 256, 256>>>(W_in,  (__nv_bfloat16*)p_wi2, DM / 4, DP * DM / 4);
    split_B<<<(DM * DI / 4 + 255) / 256, 256>>>(W_out, (__nv_bfloat16*)p_wo2, DI / 4, DM * DI / 4);

    // 1) proj = u @ W_in^T   (M=2048, N=4480, K'=3072) — mma.sync bf16
    gemm_bf16<<<dim3(DP / 128, BT / 128), 256, GS_TOTAL>>>(
        (const __nv_bfloat16*)p_u2, (const __nv_bfloat16*)p_wi2,
        (float*)p_proj, BT, DP, K1X);

    // 2) rmsnorm + head scalars
    prep_kernel<<<BT, 128>>>(dt_bias, B_norm_w, C_norm_w);

    // 3) theta cumsum + sincos
    theta_kernel<<<dim3(NH, B_), 32>>>();

    // 4) sequential scan
    scan_kernel<<<dim3(2, NH, B_), 128>>>(B_bias, C_bias);

    // 5) gated epilogue (+ folded bf16 split of activation)
    epi_kernel<<<(BT * DI) / 256, 256>>>(D_param);

    // 6) out = yact @ W_out^T  (M=2048, N=1024, K'=6144) — mma.sync bf16
    gemm_bf16<<<dim3(DM / 128, BT / 128), 256, GS_TOTAL>>>(
        (const __nv_bfloat16*)p_y2, (const __nv_bfloat16*)p_wo2,
        out, BT, DM, K2X);
}

// round 5
// speedup vs baseline: 2.3971x; 1.8198x over previous
#include <cuda_runtime.h>
#include <cuda_bf16.h>
#include <math.h>
#include <stdint.h>

#define B_  2
#define L_  1024
#define DM  1024
#define DI  2048
#define NH  32
#define HD  64
#define DS  128
#define NA  32
#define DP  4480   // 2*DI + 2*DS + 3*NH + NA
#define BT  (B_*L_)

#define K1X (3*DM)      // gemm1 folded K' = 3072
#define K2X (3*DI)      // gemm2 folded K' = 6144

// ---------------- device scratch ----------------
__device__ float g_proj[(size_t)BT * DP];
__device__ float g_Bn  [BT * DS];
__device__ float g_Cn  [BT * DS];
__device__ float g_dt  [BT * NH];
__device__ float g_gd  [BT * NH];
__device__ float g_lam [BT * NH];
__device__ float g_cos [BT * NH * NA];
__device__ float g_sin [BT * NH * NA];
__device__ float g_y   [(size_t)BT * DI];
__device__ float g_csum[B_ * 32 * NH * NA];   // chunk sums
__device__ float g_cpre[B_ * 32 * NH * NA];   // exclusive chunk prefixes

__device__ __nv_bfloat16 g_u2 [(size_t)BT * K1X];
__device__ __nv_bfloat16 g_Wi2[(size_t)DP * K1X];
__device__ __nv_bfloat16 g_y2 [(size_t)BT * K2X];
__device__ __nv_bfloat16 g_Wo2[(size_t)DM * K2X];

__device__ __forceinline__ float softplusf(float x) {
    return (x > 20.f) ? x : log1pf(expf(x));
}
__device__ __forceinline__ uint32_t smem_u32(const void* p) {
    uint32_t a;
    asm("{ .reg .u64 t; cvta.to.shared.u64 t, %1; cvt.u32.u64 %0, t; }" : "=r"(a) : "l"(p));
    return a;
}

#define CP_ASYNC16(dst, src) \
    asm volatile("cp.async.cg.shared.global [%0], [%1], 16;" :: "r"(dst), "l"(src))
#define CP_ASYNC4(dst, src) \
    asm volatile("cp.async.ca.shared.global [%0], [%1], 4;" :: "r"(dst), "l"(src))
#define CP_COMMIT() asm volatile("cp.async.commit_group;")
#define CP_WAIT1()  asm volatile("cp.async.wait_group 1;")
#define CP_WAIT0()  asm volatile("cp.async.wait_group 0;")

__device__ __forceinline__ void ldsm_x4(uint32_t* r, uint32_t addr) {
    asm volatile("ldmatrix.sync.aligned.m8n8.x4.shared.b16 {%0,%1,%2,%3}, [%4];"
        : "=r"(r[0]), "=r"(r[1]), "=r"(r[2]), "=r"(r[3]) : "r"(addr));
}
__device__ __forceinline__ void mma16816(float* d, const uint32_t* a, const uint32_t* b) {
    asm volatile(
        "mma.sync.aligned.m16n8k16.row.col.f32.bf16.bf16.f32 "
        "{%0,%1,%2,%3},{%4,%5,%6,%7},{%8,%9},{%0,%1,%2,%3};"
        : "+f"(d[0]), "+f"(d[1]), "+f"(d[2]), "+f"(d[3])
        : "r"(a[0]), "r"(a[1]), "r"(a[2]), "r"(a[3]), "r"(b[0]), "r"(b[1]));
}

// ---------------- split kernels: f32 -> folded bf16 rows ----------------
__global__ __launch_bounds__(256) void split_A(
    const float* __restrict__ src, __nv_bfloat16* __restrict__ dst, int Kq, int n4)
{
    int i = blockIdx.x * 256 + threadIdx.x;
    if (i >= n4) return;
    int row = i / Kq, k4 = (i - row * Kq) * 4;
    float4 v = *(const float4*)(src + (size_t)row * (Kq * 4) + k4);
    __nv_bfloat162 h01 = __floats2bfloat162_rn(v.x, v.y);
    __nv_bfloat162 h23 = __floats2bfloat162_rn(v.z, v.w);
    __nv_bfloat162 l01 = __floats2bfloat162_rn(v.x - __low2float(h01), v.y - __high2float(h01));
    __nv_bfloat162 l23 = __floats2bfloat162_rn(v.z - __low2float(h23), v.w - __high2float(h23));
    const int K = Kq * 4;
    __nv_bfloat162* d0 = (__nv_bfloat162*)(dst + (size_t)row * 3 * K + k4);
    __nv_bfloat162* d1 = (__nv_bfloat162*)(dst + (size_t)row * 3 * K + K + k4);
    __nv_bfloat162* d2 = (__nv_bfloat162*)(dst + (size_t)row * 3 * K + 2 * K + k4);
    d0[0] = h01; d0[1] = h23;
    d1[0] = l01; d1[1] = l23;
    d2[0] = h01; d2[1] = h23;
}
__global__ __launch_bounds__(256) void split_B(
    const float* __restrict__ src, __nv_bfloat16* __restrict__ dst, int Kq, int n4)
{
    int i = blockIdx.x * 256 + threadIdx.x;
    if (i >= n4) return;
    int row = i / Kq, k4 = (i - row * Kq) * 4;
    float4 v = *(const float4*)(src + (size_t)row * (Kq * 4) + k4);
    __nv_bfloat162 h01 = __floats2bfloat162_rn(v.x, v.y);
    __nv_bfloat162 h23 = __floats2bfloat162_rn(v.z, v.w);
    __nv_bfloat162 l01 = __floats2bfloat162_rn(v.x - __low2float(h01), v.y - __high2float(h01));
    __nv_bfloat162 l23 = __floats2bfloat162_rn(v.z - __low2float(h23), v.w - __high2float(h23));
    const int K = Kq * 4;
    __nv_bfloat162* d0 = (__nv_bfloat162*)(dst + (size_t)row * 3 * K + k4);
    __nv_bfloat162* d1 = (__nv_bfloat162*)(dst + (size_t)row * 3 * K + K + k4);
    __nv_bfloat162* d2 = (__nv_bfloat162*)(dst + (size_t)row * 3 * K + 2 * K + k4);
    d0[0] = h01; d0[1] = h23;
    d1[0] = h01; d1[1] = h23;
    d2[0] = l01; d2[1] = l23;
}

// ---------------- bf16 mma.sync GEMM (unchanged from R3) ----------------
#define GS_STAGE 32768
#define GS_TOTAL (2 * GS_STAGE + 1024)

__global__ __launch_bounds__(256) void gemm_bf16(
    const __nv_bfloat16* __restrict__ A, const __nv_bfloat16* __restrict__ Bm,
    float* __restrict__ C, int M, int N, int K)
{
    extern __shared__ char dynsmem[];
    const int tid = threadIdx.x;
    const int wid = tid >> 5, lane = tid & 31;
    const int bm = blockIdx.y * 128, bn = blockIdx.x * 128;
    const int m_warp = (wid >> 1) * 32, n_warp = (wid & 1) * 64;

    uint32_t raw = smem_u32(dynsmem);
    const uint32_t sbase = (raw + 1023u) & ~1023u;

    uint32_t psw[4];
    const __nv_bfloat16 *Ap[4], *Bp[4];
#pragma unroll
    for (int i = 0; i < 4; i++) {
        const int chunk = tid + i * 256;
        const int row = chunk >> 3, c = chunk & 7;
        psw[i] = row * 128 + ((c ^ (row & 7)) << 4);
        Ap[i] = A  + (size_t)(bm + row) * K + c * 8;
        Bp[i] = Bm + (size_t)(bn + row) * K + c * 8;
    }

    const int khA = lane >> 4;
    const int rA0 = m_warp + (lane & 15), rA1 = rA0 + 16;
    const uint32_t offA0 = rA0 * 128, offA1 = rA1 * 128;
    const int x7A0 = rA0 & 7, x7A1 = rA1 & 7;
    const int khB = (lane >> 3) & 1;
    const int rb_off = (lane & 7) + ((lane >> 4) << 3);
    uint32_t offB[4]; int x7B[4];
#pragma unroll
    for (int np = 0; np < 4; np++) {
        const int r = n_warp + np * 16 + rb_off;
        offB[np] = r * 128; x7B[np] = r & 7;
    }

    float acc[2][8][4];
#pragma unroll
    for (int mt = 0; mt < 2; mt++)
#pragma unroll
        for (int nt = 0; nt < 8; nt++)
#pragma unroll
            for (int e = 0; e < 4; e++) acc[mt][nt][e] = 0.f;

    const int nk = K >> 6;
    {
        const uint32_t s = sbase;
#pragma unroll
        for (int i = 0; i < 4; i++) {
            CP_ASYNC16(s + psw[i], Ap[i]);
            CP_ASYNC16(s + 16384 + psw[i], Bp[i]);
        }
        CP_COMMIT();
    }

    for (int kc = 0; kc < nk; kc++) {
        const int buf = kc & 1;
        if (kc + 1 < nk) {
            const uint32_t s = sbase + (buf ^ 1) * GS_STAGE;
            const int ko = (kc + 1) << 6;
#pragma unroll
            for (int i = 0; i < 4; i++) {
                CP_ASYNC16(s + psw[i], Ap[i] + ko);
                CP_ASYNC16(s + 16384 + psw[i], Bp[i] + ko);
            }
            CP_COMMIT();
            CP_WAIT1();
        } else {
            CP_WAIT0();
        }
        __syncthreads();

        const uint32_t sA = sbase + buf * GS_STAGE;
        const uint32_t sB = sA + 16384;
#pragma unroll
        for (int ks = 0; ks < 4; ks++) {
            uint32_t a0[4], a1[4];
            const int cA = 2 * ks + khA;
            ldsm_x4(a0, sA + offA0 + ((cA ^ x7A0) << 4));
            ldsm_x4(a1, sA + offA1 + ((cA ^ x7A1) << 4));
            uint32_t b[8][2];
            const int cB = 2 * ks + khB;
#pragma unroll
            for (int np = 0; np < 4; np++) {
                uint32_t r[4];
                ldsm_x4(r, sB + offB[np] + ((cB ^ x7B[np]) << 4));
                b[2 * np][0] = r[0]; b[2 * np][1] = r[1];
                b[2 * np + 1][0] = r[2]; b[2 * np + 1][1] = r[3];
            }
#pragma unroll
            for (int nt = 0; nt < 8; nt++) {
                mma16816(acc[0][nt], a0, b[nt]);
                mma16816(acc[1][nt], a1, b[nt]);
            }
        }
        __syncthreads();
    }

    const int tr = lane >> 2, tc = (lane & 3) * 2;
#pragma unroll
    for (int mt = 0; mt < 2; mt++) {
        const int row0 = bm + m_warp + mt * 16 + tr;
#pragma unroll
        for (int nt = 0; nt < 8; nt++) {
            const int col = bn + n_warp + nt * 8 + tc;
            *(float2*)(C + (size_t)row0 * N + col)       = make_float2(acc[mt][nt][0], acc[mt][nt][1]);
            *(float2*)(C + (size_t)(row0 + 8) * N + col) = make_float2(acc[mt][nt][2], acc[mt][nt][3]);
        }
    }
}

// ---------------- prep ----------------
__global__ __launch_bounds__(128) void prep_kernel(
    const float* __restrict__ dt_bias,
    const float* __restrict__ Bnw, const float* __restrict__ Cnw)
{
    const int bt = blockIdx.x;
    const int n  = threadIdx.x;
    const size_t base = (size_t)bt * DP;

    float Bv = g_proj[base + 2 * DI + n];
    float Cv = g_proj[base + 2 * DI + DS + n];
    float sb = Bv * Bv, sc = Cv * Cv;
#pragma unroll
    for (int o = 16; o > 0; o >>= 1) {
        sb += __shfl_xor_sync(0xffffffffu, sb, o);
        sc += __shfl_xor_sync(0xffffffffu, sc, o);
    }
    __shared__ float red[2][4];
    const int w = n >> 5, ln = n & 31;
    if (ln == 0) { red[0][w] = sb; red[1][w] = sc; }
    __syncthreads();
    float tb = red[0][0] + red[0][1] + red[0][2] + red[0][3];
    float tc = red[1][0] + red[1][1] + red[1][2] + red[1][3];

    g_Bn[bt * DS + n] = Bv * rsqrtf(tb * (1.f / DS) + 1e-5f) * Bnw[n];
    g_Cn[bt * DS + n] = Cv * rsqrtf(tc * (1.f / DS) + 1e-5f) * Cnw[n];

    if (n < NH) {
        float dd = g_proj[base + 2 * DI + 2 * DS + n];
        float dA = g_proj[base + 2 * DI + 2 * DS + NH + n];
        float tr = g_proj[base + 2 * DI + 2 * DS + 2 * NH + n];
        float dt = softplusf(dd + dt_bias[n]);
        float a  = -softplusf(dA);
        a = fminf(a, -1e-4f);
        g_dt [bt * NH + n] = dt;
        g_gd [bt * NH + n] = expf(a * dt);
        g_lam[bt * NH + n] = 1.f / (1.f + expf(-tr));
    }
}

// ---------------- theta: parallel 3-pass ----------------
// A: per (b, chunk) block computes chunkSum[h][j] = sum_s dt[s,h]*ang[s,j]
__global__ __launch_bounds__(1024) void thetaA_kernel()
{
    const int c = blockIdx.x, b = blockIdx.y;
    __shared__ float sdt[1024], sang[1024];
    const int i = threadIdx.x;
    const int bt0 = b * L_ + c * 32;
    sdt[i] = g_dt[bt0 * NH + i];
    const int s = i >> 5, j = i & 31;
    sang[i] = g_proj[(size_t)(bt0 + s) * DP + (DP - NA) + j];
    __syncthreads();
    const int h = i >> 5;
    float acc = 0.f;
#pragma unroll
    for (int ss = 0; ss < 32; ss++)
        acc = fmaf(sdt[ss * 32 + h], sang[ss * 32 + j], acc);
    g_csum[(b * 32 + c) * 1024 + i] = acc;
}

// B: per b, serial exclusive prefix over 32 chunks (coalesced across (h,j))
__global__ __launch_bounds__(1024) void thetaB_kernel()
{
    const int b = blockIdx.x, i = threadIdx.x;
    float run = 0.f;
    for (int c = 0; c < 32; c++) {
        float v = g_csum[(b * 32 + c) * 1024 + i];
        g_cpre[(b * 32 + c) * 1024 + i] = run;
        run += v;
    }
}

// C: per (b, chunk) recompute inclusive cumsum + __sincosf, store cos/sin
__global__ __launch_bounds__(1024) void thetaC_kernel()
{
    const int c = blockIdx.x, b = blockIdx.y;
    __shared__ float sdt[1024], sang[1024];
    const int i = threadIdx.x;
    const int bt0 = b * L_ + c * 32;
    sdt[i] = g_dt[bt0 * NH + i];
    const int s0 = i >> 5, j = i & 31;
    sang[i] = g_proj[(size_t)(bt0 + s0) * DP + (DP - NA) + j];
    __syncthreads();
    const int h = i >> 5;
    float run = g_cpre[(b * 32 + c) * 1024 + i];
#pragma unroll
    for (int s = 0; s < 32; s++) {
        run = fmaf(sdt[s * 32 + h], sang[s * 32 + j], run);
        float sn, cs;
        __sincosf(run, &sn, &cs);
        const int o = (bt0 + s) * 1024 + i;
        g_cos[o] = cs;
        g_sin[o] = sn;
    }
}

// ---------------- tiled sequential SSM scan (cp.async double-buffered) ----------------
#define ST 16
#define NTILE (L_ / ST)

__global__ __launch_bounds__(128) void scan_kernel(
    const float* __restrict__ Bbias, const float* __restrict__ Cbias)
{
    const int phalf = blockIdx.x;
    const int h = blockIdx.y;
    const int b = blockIdx.z;
    const int tid = threadIdx.x;
    const int lp = tid >> 2;
    const int nq = tid & 3;
    const int n0 = nq * 32;
    const int pstart = phalf * 32;

    __shared__ float sB[2][ST][128];
    __shared__ float sC[2][ST][128];
    __shared__ float sCs[2][ST][32];
    __shared__ float sSn[2][ST][32];
    __shared__ float sX[2][ST][32];
    __shared__ float sScal[2][3][ST];

    // rope-stage role
    const int nn = tid & 63;
    const float* biasPtr = (tid < 64) ? Bbias : Cbias;
    float ba1, ba2;
    if (nn < 32) { ba1 = biasPtr[h * DS + nn];      ba2 = biasPtr[h * DS + nn + 32]; }
    else         { ba1 = biasPtr[h * DS + nn + 32]; ba2 = biasPtr[h * DS + nn + 64]; }

#define PREFETCH(k, pbuf) do {                                                   \
        const int bt0_ = b * L_ + (k) * ST;                                      \
        _Pragma("unroll")                                                        \
        for (int r = 0; r < 4; r++) {                                            \
            const int q = tid + r * 128, tp = q >> 5, seg = q & 31;              \
            CP_ASYNC16(smem_u32(&sB[pbuf][tp][seg * 4]),                         \
                       &g_Bn[(bt0_ + tp) * DS + seg * 4]);                       \
            CP_ASYNC16(smem_u32(&sC[pbuf][tp][seg * 4]),                         \
                       &g_Cn[(bt0_ + tp) * DS + seg * 4]);                       \
        }                                                                        \
        {                                                                        \
            const int tp = tid >> 3, seg = tid & 7;                              \
            CP_ASYNC16(smem_u32(&sCs[pbuf][tp][seg * 4]),                        \
                       &g_cos[((bt0_ + tp) * NH + h) * NA + seg * 4]);           \
            CP_ASYNC16(smem_u32(&sSn[pbuf][tp][seg * 4]),                        \
                       &g_sin[((bt0_ + tp) * NH + h) * NA + seg * 4]);           \
            CP_ASYNC16(smem_u32(&sX[pbuf][tp][seg * 4]),                         \
                       &g_proj[(size_t)(bt0_ + tp) * DP + DI + h * HD + pstart + seg * 4]); \
        }                                                                        \
        if (tid < 48) {                                                          \
            const int which = tid >> 4, tp = tid & 15;                           \
            const float* srcs = (which == 0) ? g_dt : (which == 1) ? g_gd : g_lam; \
            CP_ASYNC4(smem_u32(&sScal[pbuf][which][tp]),                         \
                      &srcs[(bt0_ + tp) * NH + h]);                              \
        }                                                                        \
        CP_COMMIT();                                                             \
    } while (0)

    float hreg[32], Bp[32];
#pragma unroll
    for (int i = 0; i < 32; i++) { hreg[i] = 0.f; Bp[i] = 0.f; }
    float xprev = 0.f;

    PREFETCH(0, 0);

    for (int k = 0; k < NTILE; k++) {
        const int buf = k & 1;
        if (k + 1 < NTILE) {
            PREFETCH(k + 1, buf ^ 1);
            CP_WAIT1();
        } else {
            CP_WAIT0();
        }
        __syncthreads();

        // ---- bias + RoPE stage (in place on tile) ----
        {
            float* mat = (tid < 64) ? &sB[buf][0][0] : &sC[buf][0][0];
#pragma unroll
            for (int tp = 0; tp < ST; tp++) {
                float* rb = mat + tp * 128;
                if (nn < 32) {
                    const float cv = sCs[buf][tp][nn], sv = sSn[buf][tp][nn];
                    const float v1 = rb[nn] + ba1, v2 = rb[nn + 32] + ba2;
                    rb[nn]      = v1 * cv - v2 * sv;
                    rb[nn + 32] = v1 * sv + v2 * cv;
                } else {
                    rb[nn + 32] += ba1;
                    rb[nn + 64] += ba2;
                }
            }
        }
        __syncthreads();

        // ---- compute 16 timesteps from the tile ----
#pragma unroll
        for (int tp = 0; tp < ST; tp++) {
            const float dt  = sScal[buf][0][tp];
            const float g   = sScal[buf][1][tp];
            const float lam = sScal[buf][2][tp];
            const float xc  = sX[buf][tp][lp];
            const float c1 = dt * lam * xc;
            const float c2 = dt * (1.f - lam) * g * xprev;
            float y = 0.f;
            const float4* pB4 = (const float4*)&sB[buf][tp][n0];
            const float4* pC4 = (const float4*)&sC[buf][tp][n0];
#pragma unroll
            for (int q = 0; q < 8; q++) {
                float4 bv = pB4[q];
                float4 cv = pC4[q];
                const int i = q * 4;
                hreg[i + 0] = fmaf(g, hreg[i + 0], fmaf(c1, bv.x, c2 * Bp[i + 0]));
                y = fmaf(hreg[i + 0], cv.x, y);
                Bp[i + 0] = bv.x;
                hreg[i + 1] = fmaf(g, hreg[i + 1], fmaf(c1, bv.y, c2 * Bp[i + 1]));
                y = fmaf(hreg[i + 1], cv.y, y);
                Bp[i + 1] = bv.y;
                hreg[i + 2] = fmaf(g, hreg[i + 2], fmaf(c1, bv.z, c2 * Bp[i + 2]));
                y = fmaf(hreg[i + 2], cv.z, y);
                Bp[i + 2] = bv.z;
                hreg[i + 3] = fmaf(g, hreg[i + 3], fmaf(c1, bv.w, c2 * Bp[i + 3]));
                y = fmaf(hreg[i + 3], cv.w, y);
                Bp[i + 3] = bv.w;
            }
            xprev = xc;
            y += __shfl_xor_sync(0xffffffffu, y, 1);
            y += __shfl_xor_sync(0xffffffffu, y, 2);
            if (nq == 0)
                g_y[(size_t)(b * L_ + k * ST + tp) * DI + h * HD + pstart + lp] = y;
        }
        __syncthreads();   // protect this buffer before prefetch(k+2) overwrites it
    }
#undef PREFETCH
}

// ---------------- epilogue: yact = (y + D[h]*x) * silu(z) -> folded bf16 ----------------
__global__ __launch_bounds__(256) void epi_kernel(const float* __restrict__ Dp)
{
    const int idx = blockIdx.x * 256 + threadIdx.x;
    const int bt = idx >> 11;
    const int c  = idx & 2047;
    const int h  = c >> 6;
    float y = g_y[idx];
    float x = g_proj[(size_t)bt * DP + DI + c];
    float z = g_proj[(size_t)bt * DP + c];
    float sil = z / (1.f + expf(-z));
    float v = (y + Dp[h] * x) * sil;
    __nv_bfloat16 hh = __float2bfloat16(v);
    __nv_bfloat16 ll = __float2bfloat16(v - __bfloat162float(hh));
    const size_t rb = (size_t)bt * K2X;
    g_y2[rb + c]          = hh;
    g_y2[rb + DI + c]     = ll;
    g_y2[rb + 2 * DI + c] = hh;
}

// ---------------- launch ----------------
extern "C" void kernel_launch(void* const* d_in, const int* in_sizes, int n_in,
                              void* d_out, int out_size)
{
    (void)in_sizes; (void)n_in; (void)out_size;
    const float* u        = (const float*)d_in[0];
    const float* W_in     = (const float*)d_in[1];
    const float* W_out    = (const float*)d_in[2];
    const float* dt_bias  = (const float*)d_in[3];
    const float* B_bias   = (const float*)d_in[4];
    const float* C_bias   = (const float*)d_in[5];
    const float* B_norm_w = (const float*)d_in[6];
    const float* C_norm_w = (const float*)d_in[7];
    const float* D_param  = (const float*)d_in[8];
    float* out = (float*)d_out;

    void *p_proj, *p_u2, *p_wi2, *p_y2, *p_wo2;
    cudaGetSymbolAddress(&p_proj, g_proj);
    cudaGetSymbolAddress(&p_u2,  g_u2);
    cudaGetSymbolAddress(&p_wi2, g_Wi2);
    cudaGetSymbolAddress(&p_y2,  g_y2);
    cudaGetSymbolAddress(&p_wo2, g_Wo2);

    cudaFuncSetAttribute(gemm_bf16, cudaFuncAttributeMaxDynamicSharedMemorySize, GS_TOTAL);

    // 0) folded bf16 splits
    split_A<<<(BT * DM / 4 + 255) / 256, 256>>>(u,     (__nv_bfloat16*)p_u2,  DM / 4, BT * DM / 4);
    split_B<<<(DP * DM / 4 + 255) / 256, 256>>>(W_in,  (__nv_bfloat16*)p_wi2, DM / 4, DP * DM / 4);
    split_B<<<(DM * DI / 4 + 255) / 256, 256>>>(W_out, (__nv_bfloat16*)p_wo2, DI / 4, DM * DI / 4);

    // 1) proj = u @ W_in^T
    gemm_bf16<<<dim3(DP / 128, BT / 128), 256, GS_TOTAL>>>(
        (const __nv_bfloat16*)p_u2, (const __nv_bfloat16*)p_wi2,
        (float*)p_proj, BT, DP, K1X);

    // 2) rmsnorm + head scalars
    prep_kernel<<<BT, 128>>>(dt_bias, B_norm_w, C_norm_w);

    // 3) theta: parallel chunked cumsum + sincos
    thetaA_kernel<<<dim3(32, B_), 1024>>>();
    thetaB_kernel<<<B_, 1024>>>();
    thetaC_kernel<<<dim3(32, B_), 1024>>>();

    // 4) tiled sequential scan
    scan_kernel<<<dim3(2, NH, B_), 128>>>(B_bias, C_bias);

    // 5) gated epilogue
    epi_kernel<<<(BT * DI) / 256, 256>>>(D_param);

    // 6) out = yact @ W_out^T
    gemm_bf16<<<dim3(DM / 128, BT / 128), 256, GS_TOTAL>>>(
        (const __nv_bfloat16*)p_y2, (const __nv_bfloat16*)p_wo2,
        out, BT, DM, K2X);
}

// round 7
// speedup vs baseline: 2.5557x; 1.0661x over previous
#include <cuda_runtime.h>
#include <cuda_bf16.h>
#include <math.h>
#include <stdint.h>

#define B_  2
#define L_  1024
#define DM  1024
#define DI  2048
#define NH  32
#define HD  64
#define DS  128
#define NA  32
#define DP  4480   // 2*DI + 2*DS + 3*NH + NA
#define BT  (B_*L_)

#define K1X (3*DM)      // gemm1 folded K' = 3072
#define K2X (3*DI)      // gemm2 folded K' = 6144

// ---------------- device scratch ----------------
__device__ float g_proj[(size_t)BT * DP];
__device__ float g_Bn  [BT * DS];
__device__ float g_Cn  [BT * DS];
__device__ float g_dt  [BT * NH];
__device__ float g_gd  [BT * NH];
__device__ float g_lam [BT * NH];
__device__ float g_cos [BT * NH * NA];
__device__ float g_sin [BT * NH * NA];
__device__ float g_y   [(size_t)BT * DI];
__device__ float g_csum[B_ * 32 * NH * NA];
__device__ float g_cpre[B_ * 32 * NH * NA];

__device__ __nv_bfloat16 g_u2 [(size_t)BT * K1X];
__device__ __nv_bfloat16 g_Wi2[(size_t)DP * K1X];
__device__ __nv_bfloat16 g_y2 [(size_t)BT * K2X];
__device__ __nv_bfloat16 g_Wo2[(size_t)DM * K2X];

typedef unsigned long long ull;

__device__ __forceinline__ float softplusf(float x) {
    return (x > 20.f) ? x : log1pf(expf(x));
}
__device__ __forceinline__ uint32_t smem_u32(const void* p) {
    uint32_t a;
    asm("{ .reg .u64 t; cvta.to.shared.u64 t, %1; cvt.u32.u64 %0, t; }" : "=r"(a) : "l"(p));
    return a;
}

// ---- packed f32x2 helpers (sm_100+ baseline PTX) ----
__device__ __forceinline__ ull pk2(float v) {
    ull r; asm("mov.b64 %0, {%1, %1};" : "=l"(r) : "f"(v)); return r;
}
__device__ __forceinline__ ull fma2(ull a, ull b, ull c) {
    ull d; asm("fma.rn.f32x2 %0, %1, %2, %3;" : "=l"(d) : "l"(a), "l"(b), "l"(c)); return d;
}
__device__ __forceinline__ ull mul2(ull a, ull b) {
    ull d; asm("mul.rn.f32x2 %0, %1, %2;" : "=l"(d) : "l"(a), "l"(b)); return d;
}
__device__ __forceinline__ float sum2(ull a) {
    float x, y;
    asm("mov.b64 {%0, %1}, %2;" : "=f"(x), "=f"(y) : "l"(a));
    return x + y;
}

#define CP_ASYNC16(dst, src) \
    asm volatile("cp.async.cg.shared.global [%0], [%1], 16;" :: "r"(dst), "l"(src))
#define CP_ASYNC4(dst, src) \
    asm volatile("cp.async.ca.shared.global [%0], [%1], 4;" :: "r"(dst), "l"(src))
#define CP_COMMIT() asm volatile("cp.async.commit_group;")
#define CP_WAIT1()  asm volatile("cp.async.wait_group 1;")
#define CP_WAIT0()  asm volatile("cp.async.wait_group 0;")

__device__ __forceinline__ void ldsm_x4(uint32_t* r, uint32_t addr) {
    asm volatile("ldmatrix.sync.aligned.m8n8.x4.shared.b16 {%0,%1,%2,%3}, [%4];"
        : "=r"(r[0]), "=r"(r[1]), "=r"(r[2]), "=r"(r[3]) : "r"(addr));
}
__device__ __forceinline__ void mma16816(float* d, const uint32_t* a, const uint32_t* b) {
    asm volatile(
        "mma.sync.aligned.m16n8k16.row.col.f32.bf16.bf16.f32 "
        "{%0,%1,%2,%3},{%4,%5,%6,%7},{%8,%9},{%0,%1,%2,%3};"
        : "+f"(d[0]), "+f"(d[1]), "+f"(d[2]), "+f"(d[3])
        : "r"(a[0]), "r"(a[1]), "r"(a[2]), "r"(a[3]), "r"(b[0]), "r"(b[1]));
}

// ---------------- split kernels ----------------
__global__ __launch_bounds__(256) void split_A(
    const float* __restrict__ src, __nv_bfloat16* __restrict__ dst, int Kq, int n4)
{
    int i = blockIdx.x * 256 + threadIdx.x;
    if (i >= n4) return;
    int row = i / Kq, k4 = (i - row * Kq) * 4;
    float4 v = *(const float4*)(src + (size_t)row * (Kq * 4) + k4);
    __nv_bfloat162 h01 = __floats2bfloat162_rn(v.x, v.y);
    __nv_bfloat162 h23 = __floats2bfloat162_rn(v.z, v.w);
    __nv_bfloat162 l01 = __floats2bfloat162_rn(v.x - __low2float(h01), v.y - __high2float(h01));
    __nv_bfloat162 l23 = __floats2bfloat162_rn(v.z - __low2float(h23), v.w - __high2float(h23));
    const int K = Kq * 4;
    __nv_bfloat162* d0 = (__nv_bfloat162*)(dst + (size_t)row * 3 * K + k4);
    __nv_bfloat162* d1 = (__nv_bfloat162*)(dst + (size_t)row * 3 * K + K + k4);
    __nv_bfloat162* d2 = (__nv_bfloat162*)(dst + (size_t)row * 3 * K + 2 * K + k4);
    d0[0] = h01; d0[1] = h23;
    d1[0] = l01; d1[1] = l23;
    d2[0] = h01; d2[1] = h23;
}
__global__ __launch_bounds__(256) void split_B(
    const float* __restrict__ src, __nv_bfloat16* __restrict__ dst, int Kq, int n4)
{
    int i = blockIdx.x * 256 + threadIdx.x;
    if (i >= n4) return;
    int row = i / Kq, k4 = (i - row * Kq) * 4;
    float4 v = *(const float4*)(src + (size_t)row * (Kq * 4) + k4);
    __nv_bfloat162 h01 = __floats2bfloat162_rn(v.x, v.y);
    __nv_bfloat162 h23 = __floats2bfloat162_rn(v.z, v.w);
    __nv_bfloat162 l01 = __floats2bfloat162_rn(v.x - __low2float(h01), v.y - __high2float(h01));
    __nv_bfloat162 l23 = __floats2bfloat162_rn(v.z - __low2float(h23), v.w - __high2float(h23));
    const int K = Kq * 4;
    __nv_bfloat162* d0 = (__nv_bfloat162*)(dst + (size_t)row * 3 * K + k4);
    __nv_bfloat162* d1 = (__nv_bfloat162*)(dst + (size_t)row * 3 * K + K + k4);
    __nv_bfloat162* d2 = (__nv_bfloat162*)(dst + (size_t)row * 3 * K + 2 * K + k4);
    d0[0] = h01; d0[1] = h23;
    d1[0] = h01; d1[1] = h23;
    d2[0] = l01; d2[1] = l23;
}

// ---------------- bf16 mma.sync GEMM (unchanged) ----------------
#define GS_STAGE 32768
#define GS_TOTAL (2 * GS_STAGE + 1024)

__global__ __launch_bounds__(256) void gemm_bf16(
    const __nv_bfloat16* __restrict__ A, const __nv_bfloat16* __restrict__ Bm,
    float* __restrict__ C, int M, int N, int K)
{
    extern __shared__ char dynsmem[];
    const int tid = threadIdx.x;
    const int wid = tid >> 5, lane = tid & 31;
    const int bm = blockIdx.y * 128, bn = blockIdx.x * 128;
    const int m_warp = (wid >> 1) * 32, n_warp = (wid & 1) * 64;

    uint32_t raw = smem_u32(dynsmem);
    const uint32_t sbase = (raw + 1023u) & ~1023u;

    uint32_t psw[4];
    const __nv_bfloat16 *Ap[4], *Bp[4];
#pragma unroll
    for (int i = 0; i < 4; i++) {
        const int chunk = tid + i * 256;
        const int row = chunk >> 3, c = chunk & 7;
        psw[i] = row * 128 + ((c ^ (row & 7)) << 4);
        Ap[i] = A  + (size_t)(bm + row) * K + c * 8;
        Bp[i] = Bm + (size_t)(bn + row) * K + c * 8;
    }

    const int khA = lane >> 4;
    const int rA0 = m_warp + (lane & 15), rA1 = rA0 + 16;
    const uint32_t offA0 = rA0 * 128, offA1 = rA1 * 128;
    const int x7A0 = rA0 & 7, x7A1 = rA1 & 7;
    const int khB = (lane >> 3) & 1;
    const int rb_off = (lane & 7) + ((lane >> 4) << 3);
    uint32_t offB[4]; int x7B[4];
#pragma unroll
    for (int np = 0; np < 4; np++) {
        const int r = n_warp + np * 16 + rb_off;
        offB[np] = r * 128; x7B[np] = r & 7;
    }

    float acc[2][8][4];
#pragma unroll
    for (int mt = 0; mt < 2; mt++)
#pragma unroll
        for (int nt = 0; nt < 8; nt++)
#pragma unroll
            for (int e = 0; e < 4; e++) acc[mt][nt][e] = 0.f;

    const int nk = K >> 6;
    {
        const uint32_t s = sbase;
#pragma unroll
        for (int i = 0; i < 4; i++) {
            CP_ASYNC16(s + psw[i], Ap[i]);
            CP_ASYNC16(s + 16384 + psw[i], Bp[i]);
        }
        CP_COMMIT();
    }

    for (int kc = 0; kc < nk; kc++) {
        const int buf = kc & 1;
        if (kc + 1 < nk) {
            const uint32_t s = sbase + (buf ^ 1) * GS_STAGE;
            const int ko = (kc + 1) << 6;
#pragma unroll
            for (int i = 0; i < 4; i++) {
                CP_ASYNC16(s + psw[i], Ap[i] + ko);
                CP_ASYNC16(s + 16384 + psw[i], Bp[i] + ko);
            }
            CP_COMMIT();
            CP_WAIT1();
        } else {
            CP_WAIT0();
        }
        __syncthreads();

        const uint32_t sA = sbase + buf * GS_STAGE;
        const uint32_t sB = sA + 16384;
#pragma unroll
        for (int ks = 0; ks < 4; ks++) {
            uint32_t a0[4], a1[4];
            const int cA = 2 * ks + khA;
            ldsm_x4(a0, sA + offA0 + ((cA ^ x7A0) << 4));
            ldsm_x4(a1, sA + offA1 + ((cA ^ x7A1) << 4));
            uint32_t b[8][2];
            const int cB = 2 * ks + khB;
#pragma unroll
            for (int np = 0; np < 4; np++) {
                uint32_t r[4];
                ldsm_x4(r, sB + offB[np] + ((cB ^ x7B[np]) << 4));
                b[2 * np][0] = r[0]; b[2 * np][1] = r[1];
                b[2 * np + 1][0] = r[2]; b[2 * np + 1][1] = r[3];
            }
#pragma unroll
            for (int nt = 0; nt < 8; nt++) {
                mma16816(acc[0][nt], a0, b[nt]);
                mma16816(acc[1][nt], a1, b[nt]);
            }
        }
        __syncthreads();
    }

    const int tr = lane >> 2, tc = (lane & 3) * 2;
#pragma unroll
    for (int mt = 0; mt < 2; mt++) {
        const int row0 = bm + m_warp + mt * 16 + tr;
#pragma unroll
        for (int nt = 0; nt < 8; nt++) {
            const int col = bn + n_warp + nt * 8 + tc;
            *(float2*)(C + (size_t)row0 * N + col)       = make_float2(acc[mt][nt][0], acc[mt][nt][1]);
            *(float2*)(C + (size_t)(row0 + 8) * N + col) = make_float2(acc[mt][nt][2], acc[mt][nt][3]);
        }
    }
}

// ---------------- prep ----------------
__global__ __launch_bounds__(128) void prep_kernel(
    const float* __restrict__ dt_bias,
    const float* __restrict__ Bnw, const float* __restrict__ Cnw)
{
    const int bt = blockIdx.x;
    const int n  = threadIdx.x;
    const size_t base = (size_t)bt * DP;

    float Bv = g_proj[base + 2 * DI + n];
    float Cv = g_proj[base + 2 * DI + DS + n];
    float sb = Bv * Bv, sc = Cv * Cv;
#pragma unroll
    for (int o = 16; o > 0; o >>= 1) {
        sb += __shfl_xor_sync(0xffffffffu, sb, o);
        sc += __shfl_xor_sync(0xffffffffu, sc, o);
    }
    __shared__ float red[2][4];
    const int w = n >> 5, ln = n & 31;
    if (ln == 0) { red[0][w] = sb; red[1][w] = sc; }
    __syncthreads();
    float tb = red[0][0] + red[0][1] + red[0][2] + red[0][3];
    float tc = red[1][0] + red[1][1] + red[1][2] + red[1][3];

    g_Bn[bt * DS + n] = Bv * rsqrtf(tb * (1.f / DS) + 1e-5f) * Bnw[n];
    g_Cn[bt * DS + n] = Cv * rsqrtf(tc * (1.f / DS) + 1e-5f) * Cnw[n];

    if (n < NH) {
        float dd = g_proj[base + 2 * DI + 2 * DS + n];
        float dA = g_proj[base + 2 * DI + 2 * DS + NH + n];
        float tr = g_proj[base + 2 * DI + 2 * DS + 2 * NH + n];
        float dt = softplusf(dd + dt_bias[n]);
        float a  = -softplusf(dA);
        a = fminf(a, -1e-4f);
        g_dt [bt * NH + n] = dt;
        g_gd [bt * NH + n] = expf(a * dt);
        g_lam[bt * NH + n] = 1.f / (1.f + expf(-tr));
    }
}

// ---------------- theta: parallel 3-pass ----------------
__global__ __launch_bounds__(1024) void thetaA_kernel()
{
    const int c = blockIdx.x, b = blockIdx.y;
    __shared__ float sdt[1024], sang[1024];
    const int i = threadIdx.x;
    const int bt0 = b * L_ + c * 32;
    sdt[i] = g_dt[bt0 * NH + i];
    const int s = i >> 5, j = i & 31;
    sang[i] = g_proj[(size_t)(bt0 + s) * DP + (DP - NA) + j];
    __syncthreads();
    const int h = i >> 5;
    float acc = 0.f;
#pragma unroll
    for (int ss = 0; ss < 32; ss++)
        acc = fmaf(sdt[ss * 32 + h], sang[ss * 32 + j], acc);
    g_csum[(b * 32 + c) * 1024 + i] = acc;
}

__global__ __launch_bounds__(1024) void thetaB_kernel()
{
    const int b = blockIdx.x, i = threadIdx.x;
    float run = 0.f;
    for (int c = 0; c < 32; c++) {
        float v = g_csum[(b * 32 + c) * 1024 + i];
        g_cpre[(b * 32 + c) * 1024 + i] = run;
        run += v;
    }
}

__global__ __launch_bounds__(1024) void thetaC_kernel()
{
    const int c = blockIdx.x, b = blockIdx.y;
    __shared__ float sdt[1024], sang[1024];
    const int i = threadIdx.x;
    const int bt0 = b * L_ + c * 32;
    sdt[i] = g_dt[bt0 * NH + i];
    const int s0 = i >> 5, j = i & 31;
    sang[i] = g_proj[(size_t)(bt0 + s0) * DP + (DP - NA) + j];
    __syncthreads();
    const int h = i >> 5;
    float run = g_cpre[(b * 32 + c) * 1024 + i];
#pragma unroll
    for (int s = 0; s < 32; s++) {
        run = fmaf(sdt[s * 32 + h], sang[s * 32 + j], run);
        float sn, cs;
        __sincosf(run, &sn, &cs);
        const int o = (bt0 + s) * 1024 + i;
        g_cos[o] = cs;
        g_sin[o] = sn;
    }
}

// ---------------- tiled sequential SSM scan: 256 threads, f32x2 packed ----------------
// Thread layout: pp = tid>>4 (0..15), ng = tid&15. Thread owns p = {pstart+pp, pstart+pp+16},
// n-range [ng*8, ng*8+8) as 4 f32x2 pairs.
#define ST 16
#define NTILE (L_ / ST)

__global__ __launch_bounds__(256) void scan_kernel(
    const float* __restrict__ Bbias, const float* __restrict__ Cbias)
{
    const int phalf = blockIdx.x;
    const int h = blockIdx.y;
    const int b = blockIdx.z;
    const int tid = threadIdx.x;
    const int pp = tid >> 4;
    const int ng = tid & 15;
    const int n0 = ng * 8;
    const int pstart = phalf * 32;

    __shared__ float sB[2][ST][128];
    __shared__ float sC[2][ST][128];
    __shared__ float sCs[2][ST][32];
    __shared__ float sSn[2][ST][32];
    __shared__ float sX[2][ST][32];
    __shared__ float sScal[2][3][ST];

    // rope-stage role: first 128 threads -> B, next 128 -> C; 2 rows per pass
    const int nn = tid & 63;
    const int tq = (tid >> 6) & 1;
    const float* biasPtr = (tid < 128) ? Bbias : Cbias;
    float ba1, ba2;
    if (nn < 32) { ba1 = biasPtr[h * DS + nn];      ba2 = biasPtr[h * DS + nn + 32]; }
    else         { ba1 = biasPtr[h * DS + nn + 32]; ba2 = biasPtr[h * DS + nn + 64]; }

#define PREFETCH(k, pbuf) do {                                                   \
        const int bt0_ = b * L_ + (k) * ST;                                      \
        _Pragma("unroll")                                                        \
        for (int r = 0; r < 2; r++) {                                            \
            const int q = tid + r * 256, tp = q >> 5, seg = q & 31;              \
            CP_ASYNC16(smem_u32(&sB[pbuf][tp][seg * 4]),                         \
                       &g_Bn[(bt0_ + tp) * DS + seg * 4]);                       \
            CP_ASYNC16(smem_u32(&sC[pbuf][tp][seg * 4]),                         \
                       &g_Cn[(bt0_ + tp) * DS + seg * 4]);                       \
        }                                                                        \
        if (tid < 128) {                                                         \
            const int tp = tid >> 3, seg = tid & 7;                              \
            CP_ASYNC16(smem_u32(&sCs[pbuf][tp][seg * 4]),                        \
                       &g_cos[((bt0_ + tp) * NH + h) * NA + seg * 4]);           \
            CP_ASYNC16(smem_u32(&sSn[pbuf][tp][seg * 4]),                        \
                       &g_sin[((bt0_ + tp) * NH + h) * NA + seg * 4]);           \
            CP_ASYNC16(smem_u32(&sX[pbuf][tp][seg * 4]),                         \
                       &g_proj[(size_t)(bt0_ + tp) * DP + DI + h * HD + pstart + seg * 4]); \
        }                                                                        \
        if (tid < 48) {                                                          \
            const int which = tid >> 4, tp = tid & 15;                           \
            const float* srcs = (which == 0) ? g_dt : (which == 1) ? g_gd : g_lam; \
            CP_ASYNC4(smem_u32(&sScal[pbuf][which][tp]),                         \
                      &srcs[(bt0_ + tp) * NH + h]);                              \
        }                                                                        \
        CP_COMMIT();                                                             \
    } while (0)

    ull h0[4], h1[4], Bp[4];
#pragma unroll
    for (int i = 0; i < 4; i++) { h0[i] = 0ull; h1[i] = 0ull; Bp[i] = 0ull; }
    float xp0 = 0.f, xp1 = 0.f;

    PREFETCH(0, 0);

    for (int k = 0; k < NTILE; k++) {
        const int buf = k & 1;
        if (k + 1 < NTILE) {
            PREFETCH(k + 1, buf ^ 1);
            CP_WAIT1();
        } else {
            CP_WAIT0();
        }
        __syncthreads();

        // ---- bias + RoPE stage (in place on tile; 128 threads per matrix) ----
        {
            float* mat = (tid < 128) ? &sB[buf][0][0] : &sC[buf][0][0];
#pragma unroll
            for (int tp = tq; tp < ST; tp += 2) {
                float* rb = mat + tp * 128;
                if (nn < 32) {
                    const float cv = sCs[buf][tp][nn], sv = sSn[buf][tp][nn];
                    const float v1 = rb[nn] + ba1, v2 = rb[nn + 32] + ba2;
                    rb[nn]      = v1 * cv - v2 * sv;
                    rb[nn + 32] = v1 * sv + v2 * cv;
                } else {
                    rb[nn + 32] += ba1;
                    rb[nn + 64] += ba2;
                }
            }
        }
        __syncthreads();

        // ---- compute 16 timesteps from the tile ----
#pragma unroll
        for (int tp = 0; tp < ST; tp++) {
            const float dt  = sScal[buf][0][tp];
            const float g   = sScal[buf][1][tp];
            const float lam = sScal[buf][2][tp];
            const float xc0 = sX[buf][tp][pp];
            const float xc1 = sX[buf][tp][pp + 16];
            const float k1 = dt * lam;
            const float k2 = dt * (1.f - lam) * g;
            const ull g2  = pk2(g);
            const ull c1a = pk2(k1 * xc0);
            const ull c2a = pk2(k2 * xp0);
            const ull c1b = pk2(k1 * xc1);
            const ull c2b = pk2(k2 * xp1);

            const ulonglong2 b01 = *(const ulonglong2*)&sB[buf][tp][n0];
            const ulonglong2 b23 = *(const ulonglong2*)&sB[buf][tp][n0 + 4];
            const ulonglong2 c01 = *(const ulonglong2*)&sC[buf][tp][n0];
            const ulonglong2 c23 = *(const ulonglong2*)&sC[buf][tp][n0 + 4];
            const ull bv[4] = { b01.x, b01.y, b23.x, b23.y };
            const ull cv[4] = { c01.x, c01.y, c23.x, c23.y };

            ull y0 = 0ull, y1 = 0ull;
#pragma unroll
            for (int j = 0; j < 4; j++) {
                ull t0 = mul2(c2a, Bp[j]);
                t0 = fma2(c1a, bv[j], t0);
                h0[j] = fma2(g2, h0[j], t0);
                y0 = fma2(h0[j], cv[j], y0);
                ull t1 = mul2(c2b, Bp[j]);
                t1 = fma2(c1b, bv[j], t1);
                h1[j] = fma2(g2, h1[j], t1);
                y1 = fma2(h1[j], cv[j], y1);
                Bp[j] = bv[j];
            }
            xp0 = xc0; xp1 = xc1;

            float y0f = sum2(y0), y1f = sum2(y1);
#pragma unroll
            for (int o = 1; o < 16; o <<= 1) {
                y0f += __shfl_xor_sync(0xffffffffu, y0f, o);
                y1f += __shfl_xor_sync(0xffffffffu, y1f, o);
            }
            if (ng == 0) {
                const size_t ybase = (size_t)(b * L_ + k * ST + tp) * DI + h * HD + pstart;
                g_y[ybase + pp]      = y0f;
                g_y[ybase + pp + 16] = y1f;
            }
        }
        __syncthreads();   // protect this buffer before prefetch(k+2) overwrites it
    }
#undef PREFETCH
}

// ---------------- epilogue ----------------
__global__ __launch_bounds__(256) void epi_kernel(const float* __restrict__ Dp)
{
    const int idx = blockIdx.x * 256 + threadIdx.x;
    const int bt = idx >> 11;
    const int c  = idx & 2047;
    const int h  = c >> 6;
    float y = g_y[idx];
    float x = g_proj[(size_t)bt * DP + DI + c];
    float z = g_proj[(size_t)bt * DP + c];
    float sil = z / (1.f + expf(-z));
    float v = (y + Dp[h] * x) * sil;
    __nv_bfloat16 hh = __float2bfloat16(v);
    __nv_bfloat16 ll = __float2bfloat16(v - __bfloat162float(hh));
    const size_t rb = (size_t)bt * K2X;
    g_y2[rb + c]          = hh;
    g_y2[rb + DI + c]     = ll;
    g_y2[rb + 2 * DI + c] = hh;
}

// ---------------- launch ----------------
extern "C" void kernel_launch(void* const* d_in, const int* in_sizes, int n_in,
                              void* d_out, int out_size)
{
    (void)in_sizes; (void)n_in; (void)out_size;
    const float* u        = (const float*)d_in[0];
    const float* W_in     = (const float*)d_in[1];
    const float* W_out    = (const float*)d_in[2];
    const float* dt_bias  = (const float*)d_in[3];
    const float* B_bias   = (const float*)d_in[4];
    const float* C_bias   = (const float*)d_in[5];
    const float* B_norm_w = (const float*)d_in[6];
    const float* C_norm_w = (const float*)d_in[7];
    const float* D_param  = (const float*)d_in[8];
    float* out = (float*)d_out;

    void *p_proj, *p_u2, *p_wi2, *p_y2, *p_wo2;
    cudaGetSymbolAddress(&p_proj, g_proj);
    cudaGetSymbolAddress(&p_u2,  g_u2);
    cudaGetSymbolAddress(&p_wi2, g_Wi2);
    cudaGetSymbolAddress(&p_y2,  g_y2);
    cudaGetSymbolAddress(&p_wo2, g_Wo2);

    cudaFuncSetAttribute(gemm_bf16, cudaFuncAttributeMaxDynamicSharedMemorySize, GS_TOTAL);

    // 0) folded bf16 splits
    split_A<<<(BT * DM / 4 + 255) / 256, 256>>>(u,     (__nv_bfloat16*)p_u2,  DM / 4, BT * DM / 4);
    split_B<<<(DP * DM / 4 + 255) / 256, 256>>>(W_in,  (__nv_bfloat16*)p_wi2, DM / 4, DP * DM / 4);
    split_B<<<(DM * DI / 4 + 255) / 256, 256>>>(W_out, (__nv_bfloat16*)p_wo2, DI / 4, DM * DI / 4);

    // 1) proj = u @ W_in^T
    gemm_bf16<<<dim3(DP / 128, BT / 128), 256, GS_TOTAL>>>(
        (const __nv_bfloat16*)p_u2, (const __nv_bfloat16*)p_wi2,
        (float*)p_proj, BT, DP, K1X);

    // 2) rmsnorm + head scalars
    prep_kernel<<<BT, 128>>>(dt_bias, B_norm_w, C_norm_w);

    // 3) theta: parallel chunked cumsum + sincos
    thetaA_kernel<<<dim3(32, B_), 1024>>>();
    thetaB_kernel<<<B_, 1024>>>();
    thetaC_kernel<<<dim3(32, B_), 1024>>>();

    // 4) tiled sequential scan (f32x2, 256 threads)
    scan_kernel<<<dim3(2, NH, B_), 256>>>(B_bias, C_bias);

    // 5) gated epilogue
    epi_kernel<<<(BT * DI) / 256, 256>>>(D_param);

    // 6) out = yact @ W_out^T
    gemm_bf16<<<dim3(DM / 128, BT / 128), 256, GS_TOTAL>>>(
        (const __nv_bfloat16*)p_y2, (const __nv_bfloat16*)p_wo2,
        out, BT, DM, K2X);
}

// round 9
// speedup vs baseline: 4.1150x; 1.6101x over previous
#include <cuda_runtime.h>
#include <cuda_bf16.h>
#include <math.h>
#include <stdint.h>

#define B_  2
#define L_  1024
#define DM  1024
#define DI  2048
#define NH  32
#define HD  64
#define DS  128
#define NA  32
#define DP  4480   // 2*DI + 2*DS + 3*NH + NA
#define BT  (B_*L_)

#define K1X (3*DM)      // gemm1 folded K' = 3072
#define K2X (3*DI)      // gemm2 folded K' = 6144

// ---------------- device scratch ----------------
__device__ float g_proj[(size_t)BT * DP];
__device__ float g_Bn  [BT * DS];
__device__ float g_Cn  [BT * DS];
__device__ float g_dt  [BT * NH];
__device__ float g_gd  [BT * NH];
__device__ float g_lam [BT * NH];
__device__ float g_cos [BT * NH * NA];
__device__ float g_sin [BT * NH * NA];
__device__ float g_y   [(size_t)BT * DI];
__device__ float g_csum[B_ * 32 * NH * NA];
__device__ float g_cpre[B_ * 32 * NH * NA];

__device__ __nv_bfloat16 g_u2 [(size_t)BT * K1X];
__device__ __nv_bfloat16 g_Wi2[(size_t)DP * K1X];
__device__ __nv_bfloat16 g_y2 [(size_t)BT * K2X];
__device__ __nv_bfloat16 g_Wo2[(size_t)DM * K2X];

typedef unsigned long long ull;

__device__ __forceinline__ float softplusf(float x) {
    return (x > 20.f) ? x : log1pf(expf(x));
}
__device__ __forceinline__ uint32_t smem_u32(const void* p) {
    uint32_t a;
    asm("{ .reg .u64 t; cvta.to.shared.u64 t, %1; cvt.u32.u64 %0, t; }" : "=r"(a) : "l"(p));
    return a;
}

// ---- packed f32x2 helpers ----
__device__ __forceinline__ ull pk2(float v) {
    ull r; asm("mov.b64 %0, {%1, %1};" : "=l"(r) : "f"(v)); return r;
}
__device__ __forceinline__ ull fma2(ull a, ull b, ull c) {
    ull d; asm("fma.rn.f32x2 %0, %1, %2, %3;" : "=l"(d) : "l"(a), "l"(b), "l"(c)); return d;
}
__device__ __forceinline__ ull mul2(ull a, ull b) {
    ull d; asm("mul.rn.f32x2 %0, %1, %2;" : "=l"(d) : "l"(a), "l"(b)); return d;
}
__device__ __forceinline__ float sum2(ull a) {
    float x, y;
    asm("mov.b64 {%0, %1}, %2;" : "=f"(x), "=f"(y) : "l"(a));
    return x + y;
}

#define CP_ASYNC16(dst, src) \
    asm volatile("cp.async.cg.shared.global [%0], [%1], 16;" :: "r"(dst), "l"(src))
#define CP_ASYNC4(dst, src) \
    asm volatile("cp.async.ca.shared.global [%0], [%1], 4;" :: "r"(dst), "l"(src))
#define CP_COMMIT() asm volatile("cp.async.commit_group;")
#define CP_WAIT1()  asm volatile("cp.async.wait_group 1;")
#define CP_WAIT0()  asm volatile("cp.async.wait_group 0;")

__device__ __forceinline__ void ldsm_x4(uint32_t* r, uint32_t addr) {
    asm volatile("ldmatrix.sync.aligned.m8n8.x4.shared.b16 {%0,%1,%2,%3}, [%4];"
        : "=r"(r[0]), "=r"(r[1]), "=r"(r[2]), "=r"(r[3]) : "r"(addr));
}
__device__ __forceinline__ void mma16816(float* d, const uint32_t* a, const uint32_t* b) {
    asm volatile(
        "mma.sync.aligned.m16n8k16.row.col.f32.bf16.bf16.f32 "
        "{%0,%1,%2,%3},{%4,%5,%6,%7},{%8,%9},{%0,%1,%2,%3};"
        : "+f"(d[0]), "+f"(d[1]), "+f"(d[2]), "+f"(d[3])
        : "r"(a[0]), "r"(a[1]), "r"(a[2]), "r"(a[3]), "r"(b[0]), "r"(b[1]));
}

// ---------------- split kernels ----------------
__global__ __launch_bounds__(256) void split_A(
    const float* __restrict__ src, __nv_bfloat16* __restrict__ dst, int Kq, int n4)
{
    int i = blockIdx.x * 256 + threadIdx.x;
    if (i >= n4) return;
    int row = i / Kq, k4 = (i - row * Kq) * 4;
    float4 v = *(const float4*)(src + (size_t)row * (Kq * 4) + k4);
    __nv_bfloat162 h01 = __floats2bfloat162_rn(v.x, v.y);
    __nv_bfloat162 h23 = __floats2bfloat162_rn(v.z, v.w);
    __nv_bfloat162 l01 = __floats2bfloat162_rn(v.x - __low2float(h01), v.y - __high2float(h01));
    __nv_bfloat162 l23 = __floats2bfloat162_rn(v.z - __low2float(h23), v.w - __high2float(h23));
    const int K = Kq * 4;
    __nv_bfloat162* d0 = (__nv_bfloat162*)(dst + (size_t)row * 3 * K + k4);
    __nv_bfloat162* d1 = (__nv_bfloat162*)(dst + (size_t)row * 3 * K + K + k4);
    __nv_bfloat162* d2 = (__nv_bfloat162*)(dst + (size_t)row * 3 * K + 2 * K + k4);
    d0[0] = h01; d0[1] = h23;
    d1[0] = l01; d1[1] = l23;
    d2[0] = h01; d2[1] = h23;
}
__global__ __launch_bounds__(256) void split_B(
    const float* __restrict__ src, __nv_bfloat16* __restrict__ dst, int Kq, int n4)
{
    int i = blockIdx.x * 256 + threadIdx.x;
    if (i >= n4) return;
    int row = i / Kq, k4 = (i - row * Kq) * 4;
    float4 v = *(const float4*)(src + (size_t)row * (Kq * 4) + k4);
    __nv_bfloat162 h01 = __floats2bfloat162_rn(v.x, v.y);
    __nv_bfloat162 h23 = __floats2bfloat162_rn(v.z, v.w);
    __nv_bfloat162 l01 = __floats2bfloat162_rn(v.x - __low2float(h01), v.y - __high2float(h01));
    __nv_bfloat162 l23 = __floats2bfloat162_rn(v.z - __low2float(h23), v.w - __high2float(h23));
    const int K = Kq * 4;
    __nv_bfloat162* d0 = (__nv_bfloat162*)(dst + (size_t)row * 3 * K + k4);
    __nv_bfloat162* d1 = (__nv_bfloat162*)(dst + (size_t)row * 3 * K + K + k4);
    __nv_bfloat162* d2 = (__nv_bfloat162*)(dst + (size_t)row * 3 * K + 2 * K + k4);
    d0[0] = h01; d0[1] = h23;
    d1[0] = h01; d1[1] = h23;
    d2[0] = l01; d2[1] = l23;
}

// ---------------- bf16 mma.sync GEMM (unchanged) ----------------
#define GS_STAGE 32768
#define GS_TOTAL (2 * GS_STAGE + 1024)

__global__ __launch_bounds__(256) void gemm_bf16(
    const __nv_bfloat16* __restrict__ A, const __nv_bfloat16* __restrict__ Bm,
    float* __restrict__ C, int M, int N, int K)
{
    extern __shared__ char dynsmem[];
    const int tid = threadIdx.x;
    const int wid = tid >> 5, lane = tid & 31;
    const int bm = blockIdx.y * 128, bn = blockIdx.x * 128;
    const int m_warp = (wid >> 1) * 32, n_warp = (wid & 1) * 64;

    uint32_t raw = smem_u32(dynsmem);
    const uint32_t sbase = (raw + 1023u) & ~1023u;

    uint32_t psw[4];
    const __nv_bfloat16 *Ap[4], *Bp[4];
#pragma unroll
    for (int i = 0; i < 4; i++) {
        const int chunk = tid + i * 256;
        const int row = chunk >> 3, c = chunk & 7;
        psw[i] = row * 128 + ((c ^ (row & 7)) << 4);
        Ap[i] = A  + (size_t)(bm + row) * K + c * 8;
        Bp[i] = Bm + (size_t)(bn + row) * K + c * 8;
    }

    const int khA = lane >> 4;
    const int rA0 = m_warp + (lane & 15), rA1 = rA0 + 16;
    const uint32_t offA0 = rA0 * 128, offA1 = rA1 * 128;
    const int x7A0 = rA0 & 7, x7A1 = rA1 & 7;
    const int khB = (lane >> 3) & 1;
    const int rb_off = (lane & 7) + ((lane >> 4) << 3);
    uint32_t offB[4]; int x7B[4];
#pragma unroll
    for (int np = 0; np < 4; np++) {
        const int r = n_warp + np * 16 + rb_off;
        offB[np] = r * 128; x7B[np] = r & 7;
    }

    float acc[2][8][4];
#pragma unroll
    for (int mt = 0; mt < 2; mt++)
#pragma unroll
        for (int nt = 0; nt < 8; nt++)
#pragma unroll
            for (int e = 0; e < 4; e++) acc[mt][nt][e] = 0.f;

    const int nk = K >> 6;
    {
        const uint32_t s = sbase;
#pragma unroll
        for (int i = 0; i < 4; i++) {
            CP_ASYNC16(s + psw[i], Ap[i]);
            CP_ASYNC16(s + 16384 + psw[i], Bp[i]);
        }
        CP_COMMIT();
    }

    for (int kc = 0; kc < nk; kc++) {
        const int buf = kc & 1;
        if (kc + 1 < nk) {
            const uint32_t s = sbase + (buf ^ 1) * GS_STAGE;
            const int ko = (kc + 1) << 6;
#pragma unroll
            for (int i = 0; i < 4; i++) {
                CP_ASYNC16(s + psw[i], Ap[i] + ko);
                CP_ASYNC16(s + 16384 + psw[i], Bp[i] + ko);
            }
            CP_COMMIT();
            CP_WAIT1();
        } else {
            CP_WAIT0();
        }
        __syncthreads();

        const uint32_t sA = sbase + buf * GS_STAGE;
        const uint32_t sB = sA + 16384;
#pragma unroll
        for (int ks = 0; ks < 4; ks++) {
            uint32_t a0[4], a1[4];
            const int cA = 2 * ks + khA;
            ldsm_x4(a0, sA + offA0 + ((cA ^ x7A0) << 4));
            ldsm_x4(a1, sA + offA1 + ((cA ^ x7A1) << 4));
            uint32_t b[8][2];
            const int cB = 2 * ks + khB;
#pragma unroll
            for (int np = 0; np < 4; np++) {
                uint32_t r[4];
                ldsm_x4(r, sB + offB[np] + ((cB ^ x7B[np]) << 4));
                b[2 * np][0] = r[0]; b[2 * np][1] = r[1];
                b[2 * np + 1][0] = r[2]; b[2 * np + 1][1] = r[3];
            }
#pragma unroll
            for (int nt = 0; nt < 8; nt++) {
                mma16816(acc[0][nt], a0, b[nt]);
                mma16816(acc[1][nt], a1, b[nt]);
            }
        }
        __syncthreads();
    }

    const int tr = lane >> 2, tc = (lane & 3) * 2;
#pragma unroll
    for (int mt = 0; mt < 2; mt++) {
        const int row0 = bm + m_warp + mt * 16 + tr;
#pragma unroll
        for (int nt = 0; nt < 8; nt++) {
            const int col = bn + n_warp + nt * 8 + tc;
            *(float2*)(C + (size_t)row0 * N + col)       = make_float2(acc[mt][nt][0], acc[mt][nt][1]);
            *(float2*)(C + (size_t)(row0 + 8) * N + col) = make_float2(acc[mt][nt][2], acc[mt][nt][3]);
        }
    }
}

// ---------------- prep ----------------
__global__ __launch_bounds__(128) void prep_kernel(
    const float* __restrict__ dt_bias,
    const float* __restrict__ Bnw, const float* __restrict__ Cnw)
{
    const int bt = blockIdx.x;
    const int n  = threadIdx.x;
    const size_t base = (size_t)bt * DP;

    float Bv = g_proj[base + 2 * DI + n];
    float Cv = g_proj[base + 2 * DI + DS + n];
    float sb = Bv * Bv, sc = Cv * Cv;
#pragma unroll
    for (int o = 16; o > 0; o >>= 1) {
        sb += __shfl_xor_sync(0xffffffffu, sb, o);
        sc += __shfl_xor_sync(0xffffffffu, sc, o);
    }
    __shared__ float red[2][4];
    const int w = n >> 5, ln = n & 31;
    if (ln == 0) { red[0][w] = sb; red[1][w] = sc; }
    __syncthreads();
    float tb = red[0][0] + red[0][1] + red[0][2] + red[0][3];
    float tc = red[1][0] + red[1][1] + red[1][2] + red[1][3];

    g_Bn[bt * DS + n] = Bv * rsqrtf(tb * (1.f / DS) + 1e-5f) * Bnw[n];
    g_Cn[bt * DS + n] = Cv * rsqrtf(tc * (1.f / DS) + 1e-5f) * Cnw[n];

    if (n < NH) {
        float dd = g_proj[base + 2 * DI + 2 * DS + n];
        float dA = g_proj[base + 2 * DI + 2 * DS + NH + n];
        float tr = g_proj[base + 2 * DI + 2 * DS + 2 * NH + n];
        float dt = softplusf(dd + dt_bias[n]);
        float a  = -softplusf(dA);
        a = fminf(a, -1e-4f);
        g_dt [bt * NH + n] = dt;
        g_gd [bt * NH + n] = expf(a * dt);
        g_lam[bt * NH + n] = 1.f / (1.f + expf(-tr));
    }
}

// ---------------- theta: parallel 3-pass ----------------
__global__ __launch_bounds__(1024) void thetaA_kernel()
{
    const int c = blockIdx.x, b = blockIdx.y;
    __shared__ float sdt[1024], sang[1024];
    const int i = threadIdx.x;
    const int bt0 = b * L_ + c * 32;
    sdt[i] = g_dt[bt0 * NH + i];
    const int s = i >> 5, j = i & 31;
    sang[i] = g_proj[(size_t)(bt0 + s) * DP + (DP - NA) + j];
    __syncthreads();
    const int h = i >> 5;
    float acc = 0.f;
#pragma unroll
    for (int ss = 0; ss < 32; ss++)
        acc = fmaf(sdt[ss * 32 + h], sang[ss * 32 + j], acc);
    g_csum[(b * 32 + c) * 1024 + i] = acc;
}

__global__ __launch_bounds__(1024) void thetaB_kernel()
{
    const int b = blockIdx.x, i = threadIdx.x;
    float run = 0.f;
    for (int c = 0; c < 32; c++) {
        float v = g_csum[(b * 32 + c) * 1024 + i];
        g_cpre[(b * 32 + c) * 1024 + i] = run;
        run += v;
    }
}

__global__ __launch_bounds__(1024) void thetaC_kernel()
{
    const int c = blockIdx.x, b = blockIdx.y;
    __shared__ float sdt[1024], sang[1024];
    const int i = threadIdx.x;
    const int bt0 = b * L_ + c * 32;
    sdt[i] = g_dt[bt0 * NH + i];
    const int s0 = i >> 5, j = i & 31;
    sang[i] = g_proj[(size_t)(bt0 + s0) * DP + (DP - NA) + j];
    __syncthreads();
    const int h = i >> 5;
    float run = g_cpre[(b * 32 + c) * 1024 + i];
#pragma unroll
    for (int s = 0; s < 32; s++) {
        run = fmaf(sdt[s * 32 + h], sang[s * 32 + j], run);
        float sn, cs;
        __sincosf(run, &sn, &cs);
        const int o = (bt0 + s) * 1024 + i;
        g_cos[o] = cs;
        g_sin[o] = sn;
    }
}

// ---------------- tiled sequential SSM scan ----------------
// 256 threads: pp = tid>>4 (0..15) -> p = {pstart+pp, pstart+pp+16}; ng = tid&15 -> n [ng*8, +8).
// y-reduction: one shfl_xor(8), 8-wide smem partials, batched per-tile reduce.
#define ST 16
#define NTILE (L_ / ST)

struct __align__(16) ScanSmem {
    float sB[2][ST][128];
    float sC[2][ST][128];
    float sCs[2][ST][32];
    float sSn[2][ST][32];
    float sX[2][ST][32];
    float sScal[2][3][ST];
    float sYp[ST][32][8];
};
#define SCAN_SMEM_BYTES ((int)sizeof(ScanSmem))

__global__ __launch_bounds__(256) void scan_kernel(
    const float* __restrict__ Bbias, const float* __restrict__ Cbias)
{
    extern __shared__ char dynsmem[];
    ScanSmem* s = (ScanSmem*)dynsmem;

    const int phalf = blockIdx.x;
    const int h = blockIdx.y;
    const int b = blockIdx.z;
    const int tid = threadIdx.x;
    const int pp = tid >> 4;
    const int ng = tid & 15;
    const int n0 = ng * 8;
    const int pstart = phalf * 32;

    const int nn = tid & 63;
    const int tq = (tid >> 6) & 1;
    const float* biasPtr = (tid < 128) ? Bbias : Cbias;
    float ba1, ba2;
    if (nn < 32) { ba1 = biasPtr[h * DS + nn];      ba2 = biasPtr[h * DS + nn + 32]; }
    else         { ba1 = biasPtr[h * DS + nn + 32]; ba2 = biasPtr[h * DS + nn + 64]; }

#define PREFETCH(k, pbuf) do {                                                   \
        const int bt0_ = b * L_ + (k) * ST;                                      \
        _Pragma("unroll")                                                        \
        for (int r = 0; r < 2; r++) {                                            \
            const int q = tid + r * 256, tp = q >> 5, seg = q & 31;              \
            CP_ASYNC16(smem_u32(&s->sB[pbuf][tp][seg * 4]),                      \
                       &g_Bn[(bt0_ + tp) * DS + seg * 4]);                       \
            CP_ASYNC16(smem_u32(&s->sC[pbuf][tp][seg * 4]),                      \
                       &g_Cn[(bt0_ + tp) * DS + seg * 4]);                       \
        }                                                                        \
        if (tid < 128) {                                                         \
            const int tp = tid >> 3, seg = tid & 7;                              \
            CP_ASYNC16(smem_u32(&s->sCs[pbuf][tp][seg * 4]),                     \
                       &g_cos[((bt0_ + tp) * NH + h) * NA + seg * 4]);           \
            CP_ASYNC16(smem_u32(&s->sSn[pbuf][tp][seg * 4]),                     \
                       &g_sin[((bt0_ + tp) * NH + h) * NA + seg * 4]);           \
            CP_ASYNC16(smem_u32(&s->sX[pbuf][tp][seg * 4]),                      \
                       &g_proj[(size_t)(bt0_ + tp) * DP + DI + h * HD + pstart + seg * 4]); \
        }                                                                        \
        if (tid < 48) {                                                          \
            const int which = tid >> 4, tp = tid & 15;                           \
            const float* srcs = (which == 0) ? g_dt : (which == 1) ? g_gd : g_lam; \
            CP_ASYNC4(smem_u32(&s->sScal[pbuf][which][tp]),                      \
                      &srcs[(bt0_ + tp) * NH + h]);                              \
        }                                                                        \
        CP_COMMIT();                                                             \
    } while (0)

    ull h0[4], h1[4], Bp[4];
#pragma unroll
    for (int i = 0; i < 4; i++) { h0[i] = 0ull; h1[i] = 0ull; Bp[i] = 0ull; }
    float xp0 = 0.f, xp1 = 0.f;

    PREFETCH(0, 0);

    for (int k = 0; k < NTILE; k++) {
        const int buf = k & 1;
        if (k + 1 < NTILE) {
            PREFETCH(k + 1, buf ^ 1);
            CP_WAIT1();
        } else {
            CP_WAIT0();
        }
        __syncthreads();

        // ---- bias + RoPE stage ----
        {
            float* mat = (tid < 128) ? &s->sB[buf][0][0] : &s->sC[buf][0][0];
#pragma unroll
            for (int tp = tq; tp < ST; tp += 2) {
                float* rb = mat + tp * 128;
                if (nn < 32) {
                    const float cv = s->sCs[buf][tp][nn], sv = s->sSn[buf][tp][nn];
                    const float v1 = rb[nn] + ba1, v2 = rb[nn + 32] + ba2;
                    rb[nn]      = v1 * cv - v2 * sv;
                    rb[nn + 32] = v1 * sv + v2 * cv;
                } else {
                    rb[nn + 32] += ba1;
                    rb[nn + 64] += ba2;
                }
            }
        }
        __syncthreads();

        // ---- 16 timesteps: state update, partial-y to smem ----
#pragma unroll
        for (int tp = 0; tp < ST; tp++) {
            const float dt  = s->sScal[buf][0][tp];
            const float g   = s->sScal[buf][1][tp];
            const float lam = s->sScal[buf][2][tp];
            const float xc0 = s->sX[buf][tp][pp];
            const float xc1 = s->sX[buf][tp][pp + 16];
            const float k1 = dt * lam;
            const float k2 = dt * (1.f - lam) * g;
            const ull g2  = pk2(g);
            const ull c1a = pk2(k1 * xc0);
            const ull c2a = pk2(k2 * xp0);
            const ull c1b = pk2(k1 * xc1);
            const ull c2b = pk2(k2 * xp1);

            const ulonglong2 b01 = *(const ulonglong2*)&s->sB[buf][tp][n0];
            const ulonglong2 b23 = *(const ulonglong2*)&s->sB[buf][tp][n0 + 4];
            const ulonglong2 c01 = *(const ulonglong2*)&s->sC[buf][tp][n0];
            const ulonglong2 c23 = *(const ulonglong2*)&s->sC[buf][tp][n0 + 4];
            const ull bv[4] = { b01.x, b01.y, b23.x, b23.y };
            const ull cv[4] = { c01.x, c01.y, c23.x, c23.y };

            ull y0 = 0ull, y1 = 0ull;
#pragma unroll
            for (int j = 0; j < 4; j++) {
                ull t0 = mul2(c2a, Bp[j]);
                t0 = fma2(c1a, bv[j], t0);
                h0[j] = fma2(g2, h0[j], t0);
                y0 = fma2(h0[j], cv[j], y0);
                ull t1 = mul2(c2b, Bp[j]);
                t1 = fma2(c1b, bv[j], t1);
                h1[j] = fma2(g2, h1[j], t1);
                y1 = fma2(h1[j], cv[j], y1);
                Bp[j] = bv[j];
            }
            xp0 = xc0; xp1 = xc1;

            float y0f = sum2(y0), y1f = sum2(y1);
            y0f += __shfl_xor_sync(0xffffffffu, y0f, 8);
            y1f += __shfl_xor_sync(0xffffffffu, y1f, 8);
            if ((ng & 8) == 0) {
                s->sYp[tp][pp][ng]      = y0f;
                s->sYp[tp][pp + 16][ng] = y1f;
            }
        }
        __syncthreads();

        // ---- batched per-tile reduce: 512 (t,p) pairs, float2 coalesced out ----
        {
            const int t  = tid >> 4;          // 0..15
            const int p0 = (tid & 15) * 2;    // 0,2,..,30
            float4 a0 = *(const float4*)&s->sYp[t][p0][0];
            float4 a1 = *(const float4*)&s->sYp[t][p0][4];
            float4 b0 = *(const float4*)&s->sYp[t][p0 + 1][0];
            float4 b1 = *(const float4*)&s->sYp[t][p0 + 1][4];
            float v0 = (a0.x + a0.y) + (a0.z + a0.w) + (a1.x + a1.y) + (a1.z + a1.w);
            float v1 = (b0.x + b0.y) + (b0.z + b0.w) + (b1.x + b1.y) + (b1.z + b1.w);
            *(float2*)&g_y[(size_t)(b * L_ + k * ST + t) * DI + h * HD + pstart + p0] =
                make_float2(v0, v1);
        }
        __syncthreads();   // protect tile buffers + sYp before next iteration
    }
#undef PREFETCH
}

// ---------------- epilogue ----------------
__global__ __launch_bounds__(256) void epi_kernel(const float* __restrict__ Dp)
{
    const int idx = blockIdx.x * 256 + threadIdx.x;
    const int bt = idx >> 11;
    const int c  = idx & 2047;
    const int h  = c >> 6;
    float y = g_y[idx];
    float x = g_proj[(size_t)bt * DP + DI + c];
    float z = g_proj[(size_t)bt * DP + c];
    float sil = z / (1.f + expf(-z));
    float v = (y + Dp[h] * x) * sil;
    __nv_bfloat16 hh = __float2bfloat16(v);
    __nv_bfloat16 ll = __float2bfloat16(v - __bfloat162float(hh));
    const size_t rb = (size_t)bt * K2X;
    g_y2[rb + c]          = hh;
    g_y2[rb + DI + c]     = ll;
    g_y2[rb + 2 * DI + c] = hh;
}

// ---------------- launch ----------------
extern "C" void kernel_launch(void* const* d_in, const int* in_sizes, int n_in,
                              void* d_out, int out_size)
{
    (void)in_sizes; (void)n_in; (void)out_size;
    const float* u        = (const float*)d_in[0];
    const float* W_in     = (const float*)d_in[1];
    const float* W_out    = (const float*)d_in[2];
    const float* dt_bias  = (const float*)d_in[3];
    const float* B_bias   = (const float*)d_in[4];
    const float* C_bias   = (const float*)d_in[5];
    const float* B_norm_w = (const float*)d_in[6];
    const float* C_norm_w = (const float*)d_in[7];
    const float* D_param  = (const float*)d_in[8];
    float* out = (float*)d_out;

    void *p_proj, *p_u2, *p_wi2, *p_y2, *p_wo2;
    cudaGetSymbolAddress(&p_proj, g_proj);
    cudaGetSymbolAddress(&p_u2,  g_u2);
    cudaGetSymbolAddress(&p_wi2, g_Wi2);
    cudaGetSymbolAddress(&p_y2,  g_y2);
    cudaGetSymbolAddress(&p_wo2, g_Wo2);

    cudaFuncSetAttribute(gemm_bf16, cudaFuncAttributeMaxDynamicSharedMemorySize, GS_TOTAL);
    cudaFuncSetAttribute(scan_kernel, cudaFuncAttributeMaxDynamicSharedMemorySize, SCAN_SMEM_BYTES);

    // 0) folded bf16 splits
    split_A<<<(BT * DM / 4 + 255) / 256, 256>>>(u,     (__nv_bfloat16*)p_u2,  DM / 4, BT * DM / 4);
    split_B<<<(DP * DM / 4 + 255) / 256, 256>>>(W_in,  (__nv_bfloat16*)p_wi2, DM / 4, DP * DM / 4);
    split_B<<<(DM * DI / 4 + 255) / 256, 256>>>(W_out, (__nv_bfloat16*)p_wo2, DI / 4, DM * DI / 4);

    // 1) proj = u @ W_in^T
    gemm_bf16<<<dim3(DP / 128, BT / 128), 256, GS_TOTAL>>>(
        (const __nv_bfloat16*)p_u2, (const __nv_bfloat16*)p_wi2,
        (float*)p_proj, BT, DP, K1X);

    // 2) rmsnorm + head scalars
    prep_kernel<<<BT, 128>>>(dt_bias, B_norm_w, C_norm_w);

    // 3) theta: parallel chunked cumsum + sincos
    thetaA_kernel<<<dim3(32, B_), 1024>>>();
    thetaB_kernel<<<B_, 1024>>>();
    thetaC_kernel<<<dim3(32, B_), 1024>>>();

    // 4) tiled sequential scan (f32x2 + batched y-reduce)
    scan_kernel<<<dim3(2, NH, B_), 256, SCAN_SMEM_BYTES>>>(B_bias, C_bias);

    // 5) gated epilogue
    epi_kernel<<<(BT * DI) / 256, 256>>>(D_param);

    // 6) out = yact @ W_out^T
    gemm_bf16<<<dim3(DM / 128, BT / 128), 256, GS_TOTAL>>>(
        (const __nv_bfloat16*)p_y2, (const __nv_bfloat16*)p_wo2,
        out, BT, DM, K2X);
}